// round 9
// baseline (speedup 1.0000x reference)
#include <cuda_runtime.h>
#include <math_constants.h>
#include <cstdint>

#define BATCH 4
#define SEQ   2048
#define CH    1024
#define MROWS (BATCH * SEQ)   // 8192

// ---------------- scratch (device globals; allocation-free) ----------------
// int8 limbs
static __device__ int8_t g_x0[(size_t)MROWS * CH];
static __device__ int8_t g_x1[(size_t)MROWS * CH];
static __device__ int8_t g_w0[(size_t)3 * CH * CH];
static __device__ int8_t g_w1[(size_t)3 * CH * CH];
static __device__ int8_t g_q0[(size_t)MROWS * CH];
static __device__ int8_t g_q1[(size_t)MROWS * CH];
static __device__ int8_t g_k0[(size_t)MROWS * CH];
static __device__ int8_t g_k1[(size_t)MROWS * CH];
static __device__ int8_t g_v0[(size_t)BATCH * CH * SEQ];   // V^T limbs [b*CH+c][s]
static __device__ int8_t g_v1[(size_t)BATCH * CH * SEQ];
static __device__ int8_t g_p0[(size_t)BATCH * SEQ * SEQ];
static __device__ int8_t g_p1[(size_t)BATCH * SEQ * SEQ];
// scales
static __device__ float g_sx[MROWS];
static __device__ float g_sw[3 * CH];
static __device__ float g_sq[MROWS];
static __device__ float g_sk[MROWS];
static __device__ float g_sv[BATCH * CH];
static __device__ float g_sp[BATCH * SEQ];
// fp32 intermediates
static __device__ float g_Qf[(size_t)MROWS * CH];
static __device__ float g_Kf[(size_t)MROWS * CH];
static __device__ float g_Vtf[(size_t)BATCH * CH * SEQ];
static __device__ float g_S[(size_t)BATCH * SEQ * SEQ];

// ---------------- baseline-PTX helpers ----------------
__device__ __forceinline__ uint32_t su32(const void* p) {
    uint32_t a;
    asm("{ .reg .u64 t; cvta.to.shared.u64 t, %1; cvt.u32.u64 %0, t; }"
        : "=r"(a) : "l"(p));
    return a;
}
__device__ __forceinline__ void cpasync16(uint32_t dst, const void* src) {
    asm volatile("cp.async.cg.shared.global [%0], [%1], 16;"
                 :: "r"(dst), "l"(src) : "memory");
}
__device__ __forceinline__ void cpcommit() {
    asm volatile("cp.async.commit_group;" ::: "memory");
}
template<int N> __device__ __forceinline__ void cpwait() {
    asm volatile("cp.async.wait_group %0;" :: "n"(N) : "memory");
}
__device__ __forceinline__ void ldsm4(uint32_t* r, uint32_t addr) {
    asm volatile("ldmatrix.sync.aligned.m8n8.x4.shared.b16 {%0,%1,%2,%3}, [%4];"
                 : "=r"(r[0]), "=r"(r[1]), "=r"(r[2]), "=r"(r[3]) : "r"(addr));
}
__device__ __forceinline__ void imma(int* d, const uint32_t* a, const uint32_t* b) {
    asm volatile(
        "mma.sync.aligned.m16n8k32.row.col.s32.s8.s8.s32 "
        "{%0,%1,%2,%3},{%4,%5,%6,%7},{%8,%9},{%0,%1,%2,%3};"
        : "+r"(d[0]), "+r"(d[1]), "+r"(d[2]), "+r"(d[3])
        : "r"(a[0]), "r"(a[1]), "r"(a[2]), "r"(a[3]), "r"(b[0]), "r"(b[1]));
}

// ---------------- smem geometry ----------------
// int8 tiles: 128 rows x 32 bytes, padded stride 48 B.
// Stage: A0 0, A1 6144, B0 12288, B1 18432. Stage 24576. 3 stages.
#define T_STRIDE 48
#define OFF_A1   6144
#define OFF_B0   12288
#define OFF_B1   18432
#define STAGE_SZ 24576
#define NSTAGE   3
#define SMEM_TOT (NSTAGE * STAGE_SZ)

// load one 128x32B int8 tile (256 threads, one 16B unit each x2 rows? 1/thread)
__device__ __forceinline__ void tile_ld(uint32_t sdst, const int8_t* src,
                                        int ld, int tid) {
    int r = tid >> 1, q = tid & 1;
    cpasync16(sdst + r * T_STRIDE + q * 16, src + (size_t)r * ld + q * 16);
}

__device__ __forceinline__ void chunk_ld(uint32_t sbase, int st,
                                         const int8_t* A0, const int8_t* A1,
                                         const int8_t* B0, const int8_t* B1,
                                         int lda, int ldb, int k0, int tid) {
    const uint32_t s = sbase + st * STAGE_SZ;
    tile_ld(s,          A0 + k0, lda, tid);
    tile_ld(s + OFF_A1, A1 + k0, lda, tid);
    tile_ld(s + OFF_B0, B0 + k0, ldb, tid);
    tile_ld(s + OFF_B1, B1 + k0, ldb, tid);
    cpcommit();
}

// one 128x128 x k32 chunk; warp tile 32x64. 48 IMMA / 12 LDSM per warp.
__device__ __forceinline__ void compute_chunk(uint32_t sb, int wm0, int wn0,
                                              int lane,
                                              int acc0[2][8][4], int acc1[2][8][4]) {
    const int aro = ((lane >> 3) & 1) * 8 + (lane & 7);
    const int ako = ((lane >> 4) & 1) * 16;
    const int bro = ((lane >> 4) & 1) * 8 + (lane & 7);
    const int bko = ((lane >> 3) & 1) * 16;

    uint32_t a0f[2][4], a1f[2][4], b0f[8][2], b1f[8][2];
    #pragma unroll
    for (int mi = 0; mi < 2; mi++) {
        uint32_t ra = (uint32_t)(wm0 + mi * 16 + aro) * T_STRIDE + ako;
        ldsm4(a0f[mi], sb + ra);
        ldsm4(a1f[mi], sb + OFF_A1 + ra);
    }
    #pragma unroll
    for (int np = 0; np < 4; np++) {
        uint32_t rb = (uint32_t)(wn0 + np * 16 + bro) * T_STRIDE + bko;
        uint32_t r4[4];
        ldsm4(r4, sb + OFF_B0 + rb);
        b0f[np*2][0] = r4[0]; b0f[np*2][1] = r4[1];
        b0f[np*2+1][0] = r4[2]; b0f[np*2+1][1] = r4[3];
        ldsm4(r4, sb + OFF_B1 + rb);
        b1f[np*2][0] = r4[0]; b1f[np*2][1] = r4[1];
        b1f[np*2+1][0] = r4[2]; b1f[np*2+1][1] = r4[3];
    }
    #pragma unroll
    for (int mi = 0; mi < 2; mi++)
        #pragma unroll
        for (int nj = 0; nj < 8; nj++)
            imma(acc0[mi][nj], a0f[mi], b0f[nj]);
    #pragma unroll
    for (int mi = 0; mi < 2; mi++)
        #pragma unroll
        for (int nj = 0; nj < 8; nj++)
            imma(acc1[mi][nj], a0f[mi], b1f[nj]);
    #pragma unroll
    for (int mi = 0; mi < 2; mi++)
        #pragma unroll
        for (int nj = 0; nj < 8; nj++)
            imma(acc1[mi][nj], a1f[mi], b0f[nj]);
}

__device__ __forceinline__ void gemm_main(uint32_t sbase, int NK,
                                          const int8_t* A0, const int8_t* A1,
                                          const int8_t* B0, const int8_t* B1,
                                          int lda, int ldb, int tid,
                                          int wm0, int wn0,
                                          int acc0[2][8][4], int acc1[2][8][4]) {
    const int lane = tid & 31;
    chunk_ld(sbase, 0, A0, A1, B0, B1, lda, ldb, 0, tid);
    if (NK > 1) chunk_ld(sbase, 1, A0, A1, B0, B1, lda, ldb, 32, tid);
    int st = 0;
    for (int kc = 0; kc < NK; kc++) {
        if (kc + 2 < NK) {
            int st2 = st + 2; if (st2 >= NSTAGE) st2 -= NSTAGE;
            chunk_ld(sbase, st2, A0, A1, B0, B1, lda, ldb, (kc + 2) * 32, tid);
            cpwait<2>();
        } else if (kc + 1 < NK) {
            cpwait<1>();
        } else {
            cpwait<0>();
        }
        __syncthreads();
        compute_chunk(sbase + st * STAGE_SZ, wm0, wn0, lane, acc0, acc1);
        __syncthreads();
        if (++st == NSTAGE) st = 0;
    }
}

// ---------------- row quantization helpers ----------------
__device__ __forceinline__ void quant4(float4 v, float inv, char4& c0, char4& c1) {
    float t0 = v.x * inv, t1 = v.y * inv, t2 = v.z * inv, t3 = v.w * inv;
    int q0 = __float2int_rn(t0), q1 = __float2int_rn(t1);
    int q2 = __float2int_rn(t2), q3 = __float2int_rn(t3);
    c0 = make_char4((char)q0, (char)q1, (char)q2, (char)q3);
    c1 = make_char4((char)__float2int_rn((t0 - q0) * 254.0f),
                    (char)__float2int_rn((t1 - q1) * 254.0f),
                    (char)__float2int_rn((t2 - q2) * 254.0f),
                    (char)__float2int_rn((t3 - q3) * 254.0f));
}

__device__ __forceinline__ float block_rowmax(float amax, int tid) {
    #pragma unroll
    for (int o = 16; o; o >>= 1) amax = fmaxf(amax, __shfl_xor_sync(~0u, amax, o));
    __shared__ float sm[8];
    if ((tid & 31) == 0) sm[tid >> 5] = amax;
    __syncthreads();
    float m = sm[0];
    #pragma unroll
    for (int i = 1; i < 8; i++) m = fmaxf(m, sm[i]);
    return fmaxf(m, 1e-20f);
}

// ---------------------------------------------------------------------------
// Kernel 0a: quantize x rows (8192) and W rows (3072). One block per row.
// ---------------------------------------------------------------------------
__global__ __launch_bounds__(256) void quant_in_kernel(
    const float* __restrict__ x,  const float* __restrict__ Wq,
    const float* __restrict__ Wk, const float* __restrict__ Wv) {
    const int row = blockIdx.x;
    const int tid = threadIdx.x;
    const float* src; int8_t *d0, *d1; float* sc;
    if (row < MROWS) {
        src = x + (size_t)row * CH;
        d0 = g_x0 + (size_t)row * CH; d1 = g_x1 + (size_t)row * CH;
        sc = &g_sx[row];
    } else {
        int r2 = row - MROWS;
        int mat = r2 >> 10;
        const float* W = (mat == 0) ? Wq : (mat == 1) ? Wk : Wv;
        src = W + (size_t)(r2 & 1023) * CH;
        d0 = g_w0 + (size_t)r2 * CH; d1 = g_w1 + (size_t)r2 * CH;
        sc = &g_sw[r2];
    }
    float4 v = ((const float4*)src)[tid];
    float amax = fmaxf(fmaxf(fabsf(v.x), fabsf(v.y)), fmaxf(fabsf(v.z), fabsf(v.w)));
    float s = block_rowmax(amax, tid);
    float inv = 127.0f / s;
    char4 c0, c1;
    quant4(v, inv, c0, c1);
    ((char4*)d0)[tid] = c0;
    ((char4*)d1)[tid] = c1;
    if (tid == 0) *sc = s;
}

// ---------------------------------------------------------------------------
// Kernel 0b: quantize Q/K rows (fp32 scratch, len 1024) and V^T rows (len 2048)
// ---------------------------------------------------------------------------
__global__ __launch_bounds__(256) void quant_mid_kernel() {
    const int row = blockIdx.x;
    const int tid = threadIdx.x;
    const float* src; int8_t *d0, *d1; float* sc; int nchunk;
    if (row < MROWS) {
        src = g_Qf + (size_t)row * CH;
        d0 = g_q0 + (size_t)row * CH; d1 = g_q1 + (size_t)row * CH;
        sc = &g_sq[row]; nchunk = 1;
    } else if (row < 2 * MROWS) {
        int r2 = row - MROWS;
        src = g_Kf + (size_t)r2 * CH;
        d0 = g_k0 + (size_t)r2 * CH; d1 = g_k1 + (size_t)r2 * CH;
        sc = &g_sk[r2]; nchunk = 1;
    } else {
        int r2 = row - 2 * MROWS;
        src = g_Vtf + (size_t)r2 * SEQ;
        d0 = g_v0 + (size_t)r2 * SEQ; d1 = g_v1 + (size_t)r2 * SEQ;
        sc = &g_sv[r2]; nchunk = 2;
    }
    float4 v[2];
    float amax = 0.f;
    for (int c = 0; c < nchunk; c++) {
        v[c] = ((const float4*)src)[tid + c * 256];
        amax = fmaxf(amax, fmaxf(fmaxf(fabsf(v[c].x), fabsf(v[c].y)),
                                 fmaxf(fabsf(v[c].z), fabsf(v[c].w))));
    }
    float s = block_rowmax(amax, tid);
    float inv = 127.0f / s;
    for (int c = 0; c < nchunk; c++) {
        char4 c0, c1;
        quant4(v[c], inv, c0, c1);
        ((char4*)d0)[tid + c * 256] = c0;
        ((char4*)d1)[tid + c * 256] = c1;
    }
    if (tid == 0) *sc = s;
}

// ---------------------------------------------------------------------------
// Kernel 1: QKV IMMA. grid.x = 8 n-tiles * 3 mats, grid.y = 64 m-tiles.
// ---------------------------------------------------------------------------
__global__ __launch_bounds__(256) void qkv_kernel() {
    extern __shared__ char sm[];
    const int tid = threadIdx.x, wid = tid >> 5, lane = tid & 31;
    const int mat = blockIdx.x >> 3;
    const int n0  = (blockIdx.x & 7) * 128;
    const int m0  = blockIdx.y * 128;
    const int wm0 = (wid & 3) * 32, wn0 = (wid >> 2) * 64;
    const uint32_t sbase = su32(sm);

    const int8_t* A0 = g_x0 + (size_t)m0 * CH;
    const int8_t* A1 = g_x1 + (size_t)m0 * CH;
    const int8_t* B0 = g_w0 + (size_t)mat * CH * CH + (size_t)n0 * CH;
    const int8_t* B1 = g_w1 + (size_t)mat * CH * CH + (size_t)n0 * CH;

    int acc0[2][8][4] = {}, acc1[2][8][4] = {};
    gemm_main(sbase, CH / 32, A0, A1, B0, B1, CH, CH, tid, wm0, wn0, acc0, acc1);

    const int qrow = lane >> 2, qcol = (lane & 3) * 2;
    float sB[16];
    #pragma unroll
    for (int nj = 0; nj < 8; nj++) {
        int col = n0 + wn0 + nj * 8 + qcol;
        sB[nj*2]   = g_sw[mat * CH + col];
        sB[nj*2+1] = g_sw[mat * CH + col + 1];
    }
    #pragma unroll
    for (int mi = 0; mi < 2; mi++)
        #pragma unroll
        for (int h = 0; h < 2; h++) {
            int row = m0 + wm0 + mi * 16 + qrow + h * 8;
            float sA = g_sx[row] * (1.0f / 16129.0f);
            #pragma unroll
            for (int nj = 0; nj < 8; nj++) {
                float v0 = ((float)acc0[mi][nj][h*2]   +
                            (float)acc1[mi][nj][h*2]   * (1.0f/254.0f)) * sA * sB[nj*2];
                float v1 = ((float)acc0[mi][nj][h*2+1] +
                            (float)acc1[mi][nj][h*2+1] * (1.0f/254.0f)) * sA * sB[nj*2+1];
                int col = n0 + wn0 + nj * 8 + qcol;
                if (mat == 0) {
                    *(float2*)&g_Qf[(size_t)row * CH + col] = make_float2(v0, v1);
                } else if (mat == 1) {
                    *(float2*)&g_Kf[(size_t)row * CH + col] = make_float2(v0, v1);
                } else {
                    int b = row >> 11, t = row & (SEQ - 1);
                    g_Vtf[((size_t)b * CH + col)     * SEQ + t] = v0;
                    g_Vtf[((size_t)b * CH + col + 1) * SEQ + t] = v1;
                }
            }
        }
}

// ---------------------------------------------------------------------------
// Kernel 2: scores IMMA. 128x128 tiles, skip strictly-upper. Writes fp32 S.
// ---------------------------------------------------------------------------
__global__ __launch_bounds__(256) void scores_kernel() {
    if (blockIdx.x > blockIdx.y) return;
    extern __shared__ char sm[];
    const int tid = threadIdx.x, wid = tid >> 5, lane = tid & 31;
    const int b  = blockIdx.z;
    const int s0 = blockIdx.x * 128;
    const int t0 = blockIdx.y * 128;
    const int wm0 = (wid & 3) * 32, wn0 = (wid >> 2) * 64;
    const uint32_t sbase = su32(sm);

    const size_t ar = (size_t)(b * SEQ + t0) * CH;
    const size_t br = (size_t)(b * SEQ + s0) * CH;

    int acc0[2][8][4] = {}, acc1[2][8][4] = {};
    gemm_main(sbase, CH / 32, g_q0 + ar, g_q1 + ar, g_k0 + br, g_k1 + br,
              CH, CH, tid, wm0, wn0, acc0, acc1);

    const int qrow = lane >> 2, qcol = (lane & 3) * 2;
    float sB[16];
    #pragma unroll
    for (int nj = 0; nj < 8; nj++) {
        int s = s0 + wn0 + nj * 8 + qcol;
        sB[nj*2]   = g_sk[b * SEQ + s];
        sB[nj*2+1] = g_sk[b * SEQ + s + 1];
    }
    #pragma unroll
    for (int mi = 0; mi < 2; mi++)
        #pragma unroll
        for (int h = 0; h < 2; h++) {
            int t = t0 + wm0 + mi * 16 + qrow + h * 8;
            float sA = g_sq[b * SEQ + t] * (0.03125f / 16129.0f);
            #pragma unroll
            for (int nj = 0; nj < 8; nj++) {
                int s = s0 + wn0 + nj * 8 + qcol;
                float v0 = ((float)acc0[mi][nj][h*2]   +
                            (float)acc1[mi][nj][h*2]   * (1.0f/254.0f)) * sA * sB[nj*2];
                float v1 = ((float)acc0[mi][nj][h*2+1] +
                            (float)acc1[mi][nj][h*2+1] * (1.0f/254.0f)) * sA * sB[nj*2+1];
                *(float2*)&g_S[((size_t)b * SEQ + t) * SEQ + s] = make_float2(v0, v1);
            }
        }
}

// ---------------------------------------------------------------------------
// Kernel 3: softmax; emits P int8 limbs directly (scale = inv) + g_sp.
// Thread handles 8 consecutive columns.
// ---------------------------------------------------------------------------
__global__ __launch_bounds__(256) void softmax_kernel() {
    const int t = blockIdx.x;
    const int b = blockIdx.y;
    const size_t rowb = ((size_t)b * SEQ + t) * SEQ;
    const float* Srow = g_S + rowb;
    const int tid = threadIdx.x;
    const int base = tid * 8;
    const int len = ((t >> 7) + 1) << 7;

    float v[8];
    {
        float4 a = *(const float4*)(Srow + base);
        float4 c = *(const float4*)(Srow + base + 4);
        v[0]=a.x; v[1]=a.y; v[2]=a.z; v[3]=a.w;
        v[4]=c.x; v[5]=c.y; v[6]=c.z; v[7]=c.w;
    }
    float m = -CUDART_INF_F;
    #pragma unroll
    for (int j = 0; j < 8; j++) {
        if (base + j > t) v[j] = -CUDART_INF_F;
        m = fmaxf(m, v[j]);
    }
    #pragma unroll
    for (int o = 16; o; o >>= 1) m = fmaxf(m, __shfl_xor_sync(~0u, m, o));
    __shared__ float smax[8], ssum[8];
    if ((tid & 31) == 0) smax[tid >> 5] = m;
    __syncthreads();
    m = smax[0];
    #pragma unroll
    for (int i = 1; i < 8; i++) m = fmaxf(m, smax[i]);

    float s = 0.f;
    #pragma unroll
    for (int j = 0; j < 8; j++) { v[j] = expf(v[j] - m); s += v[j]; }
    #pragma unroll
    for (int o = 16; o; o >>= 1) s += __shfl_xor_sync(~0u, s, o);
    if ((tid & 31) == 0) ssum[tid >> 5] = s;
    __syncthreads();
    s = 0.f;
    #pragma unroll
    for (int i = 0; i < 8; i++) s += ssum[i];
    const float inv = 1.0f / s;

    if (base < len) {
        // u_j = v_j in [0,1]; P = inv * u. Quantize u to 2 limbs.
        char4 c0a, c1a, c0b, c1b;
        quant4(make_float4(v[0], v[1], v[2], v[3]), 127.0f, c0a, c1a);
        quant4(make_float4(v[4], v[5], v[6], v[7]), 127.0f, c0b, c1b);
        *(char4*)&g_p0[rowb + base]     = c0a;
        *(char4*)&g_p0[rowb + base + 4] = c0b;
        *(char4*)&g_p1[rowb + base]     = c1a;
        *(char4*)&g_p1[rowb + base + 4] = c1b;
    }
    if (tid == 0) g_sp[b * SEQ + t] = inv;
}

// ---------------------------------------------------------------------------
// Kernel 4: O = P V IMMA. 128x128 tiles, K clipped at t0+128.
// ---------------------------------------------------------------------------
__global__ __launch_bounds__(256) void pv_kernel(float* __restrict__ out) {
    extern __shared__ char sm[];
    const int tid = threadIdx.x, wid = tid >> 5, lane = tid & 31;
    const int b  = blockIdx.z;
    const int c0 = blockIdx.x * 128;
    const int t0 = blockIdx.y * 128;
    const int wm0 = (wid & 3) * 32, wn0 = (wid >> 2) * 64;
    const uint32_t sbase = su32(sm);

    const int8_t* A0 = g_p0 + ((size_t)b * SEQ + t0) * SEQ;
    const int8_t* A1 = g_p1 + ((size_t)b * SEQ + t0) * SEQ;
    const int8_t* B0 = g_v0 + ((size_t)b * CH + c0) * SEQ;
    const int8_t* B1 = g_v1 + ((size_t)b * CH + c0) * SEQ;

    int acc0[2][8][4] = {}, acc1[2][8][4] = {};
    gemm_main(sbase, (t0 + 128) / 32, A0, A1, B0, B1, SEQ, SEQ, tid,
              wm0, wn0, acc0, acc1);

    const int qrow = lane >> 2, qcol = (lane & 3) * 2;
    float sB[16];
    #pragma unroll
    for (int nj = 0; nj < 8; nj++) {
        int c = c0 + wn0 + nj * 8 + qcol;
        sB[nj*2]   = g_sv[b * CH + c];
        sB[nj*2+1] = g_sv[b * CH + c + 1];
    }
    #pragma unroll
    for (int mi = 0; mi < 2; mi++)
        #pragma unroll
        for (int h = 0; h < 2; h++) {
            int t = t0 + wm0 + mi * 16 + qrow + h * 8;
            float sA = g_sp[b * SEQ + t] * (1.0f / 16129.0f);
            #pragma unroll
            for (int nj = 0; nj < 8; nj++) {
                int c = c0 + wn0 + nj * 8 + qcol;
                float v0 = ((float)acc0[mi][nj][h*2]   +
                            (float)acc1[mi][nj][h*2]   * (1.0f/254.0f)) * sA * sB[nj*2];
                float v1 = ((float)acc0[mi][nj][h*2+1] +
                            (float)acc1[mi][nj][h*2+1] * (1.0f/254.0f)) * sA * sB[nj*2+1];
                *(float2*)&out[((size_t)b * SEQ + t) * CH + c] = make_float2(v0, v1);
            }
        }
}

// ---------------------------------------------------------------------------
extern "C" void kernel_launch(void* const* d_in, const int* in_sizes, int n_in,
                              void* d_out, int out_size)
{
    const float* x  = (const float*)d_in[0];
    const float* Wq = (const float*)d_in[1];
    const float* Wk = (const float*)d_in[2];
    const float* Wv = (const float*)d_in[3];
    float* out = (float*)d_out;

    cudaFuncSetAttribute(qkv_kernel,
                         cudaFuncAttributeMaxDynamicSharedMemorySize, SMEM_TOT);
    cudaFuncSetAttribute(scores_kernel,
                         cudaFuncAttributeMaxDynamicSharedMemorySize, SMEM_TOT);
    cudaFuncSetAttribute(pv_kernel,
                         cudaFuncAttributeMaxDynamicSharedMemorySize, SMEM_TOT);

    quant_in_kernel<<<MROWS + 3 * CH, 256>>>(x, Wq, Wk, Wv);
    qkv_kernel<<<dim3(8 * 3, MROWS / 128), 256, SMEM_TOT>>>();
    quant_mid_kernel<<<2 * MROWS + BATCH * CH, 256>>>();
    scores_kernel<<<dim3(SEQ / 128, SEQ / 128, BATCH), 256, SMEM_TOT>>>();
    softmax_kernel<<<dim3(SEQ, BATCH), 256>>>();
    pv_kernel<<<dim3(CH / 128, SEQ / 128, BATCH), 256, SMEM_TOT>>>(out);
}

// round 10
// speedup vs baseline: 1.3904x; 1.3904x over previous
#include <cuda_runtime.h>
#include <cuda_bf16.h>
#include <math_constants.h>
#include <cstdint>

#define BATCH 4
#define SEQ   2048
#define CH    1024
#define MROWS (BATCH * SEQ)   // 8192

// ---------------- scratch (device globals; allocation-free) ----------------
static __device__ __nv_bfloat16 g_xh[(size_t)MROWS * CH];
static __device__ __nv_bfloat16 g_xl[(size_t)MROWS * CH];
static __device__ __nv_bfloat16 g_wh[(size_t)3 * CH * CH];
static __device__ __nv_bfloat16 g_wl[(size_t)3 * CH * CH];
static __device__ __nv_bfloat16 g_qh[(size_t)MROWS * CH];
static __device__ __nv_bfloat16 g_ql[(size_t)MROWS * CH];
static __device__ __nv_bfloat16 g_kh[(size_t)MROWS * CH];
static __device__ __nv_bfloat16 g_kl[(size_t)MROWS * CH];
static __device__ __nv_bfloat16 g_vth[(size_t)BATCH * CH * SEQ];  // V^T limbs
static __device__ __nv_bfloat16 g_vtl[(size_t)BATCH * CH * SEQ];
static __device__ float         g_S [(size_t)BATCH * SEQ * SEQ];  // logits then P
static __device__ __nv_bfloat16 g_ph[(size_t)BATCH * SEQ * SEQ];
static __device__ __nv_bfloat16 g_pl[(size_t)BATCH * SEQ * SEQ];
// fp32 copies for the SIMT path
static __device__ float g_Qf [(size_t)MROWS * CH];
static __device__ float g_Kf [(size_t)MROWS * CH];
static __device__ float g_Vtf[(size_t)BATCH * CH * SEQ];

// ---------------- baseline-PTX helpers ----------------
__device__ __forceinline__ uint32_t su32(const void* p) {
    uint32_t a;
    asm("{ .reg .u64 t; cvta.to.shared.u64 t, %1; cvt.u32.u64 %0, t; }"
        : "=r"(a) : "l"(p));
    return a;
}
__device__ __forceinline__ void cpasync16(uint32_t dst, const void* src) {
    asm volatile("cp.async.cg.shared.global [%0], [%1], 16;"
                 :: "r"(dst), "l"(src) : "memory");
}
__device__ __forceinline__ void cpcommit() {
    asm volatile("cp.async.commit_group;" ::: "memory");
}
template<int N> __device__ __forceinline__ void cpwait() {
    asm volatile("cp.async.wait_group %0;" :: "n"(N) : "memory");
}
__device__ __forceinline__ void ldsm4(uint32_t* r, uint32_t addr) {
    asm volatile("ldmatrix.sync.aligned.m8n8.x4.shared.b16 {%0,%1,%2,%3}, [%4];"
                 : "=r"(r[0]), "=r"(r[1]), "=r"(r[2]), "=r"(r[3]) : "r"(addr));
}
__device__ __forceinline__ void mma16816(float* d, const uint32_t* a,
                                         const uint32_t* b) {
    asm volatile(
        "mma.sync.aligned.m16n8k16.row.col.f32.bf16.bf16.f32 "
        "{%0,%1,%2,%3},{%4,%5,%6,%7},{%8,%9},{%0,%1,%2,%3};"
        : "+f"(d[0]), "+f"(d[1]), "+f"(d[2]), "+f"(d[3])
        : "r"(a[0]), "r"(a[1]), "r"(a[2]), "r"(a[3]), "r"(b[0]), "r"(b[1]));
}
__device__ __forceinline__ uint32_t pk(__nv_bfloat16 a, __nv_bfloat16 b) {
    uint16_t x = reinterpret_cast<uint16_t&>(a);
    uint16_t y = reinterpret_cast<uint16_t&>(b);
    return (uint32_t)x | ((uint32_t)y << 16);
}
__device__ __forceinline__ uint32_t hilo_pack(float v0, float v1, uint32_t& lo) {
    __nv_bfloat16 h0 = __float2bfloat16(v0);
    __nv_bfloat16 h1 = __float2bfloat16(v1);
    lo = pk(__float2bfloat16(v0 - __bfloat162float(h0)),
            __float2bfloat16(v1 - __bfloat162float(h1)));
    return pk(h0, h1);
}

// ---------------- bf16 3-term GEMM machinery (R6 champion config) ----------
#define T_STRIDE 80
#define OFF_AL   10240
#define OFF_BH   20480
#define OFF_BL   30720
#define STAGE_SZ 40960
#define SMEM_TOT (2 * STAGE_SZ)

__device__ __forceinline__ void tile_ld(uint32_t sdst, const __nv_bfloat16* src,
                                        int ld, int tid) {
    #pragma unroll
    for (int it = 0; it < 2; it++) {
        int u = tid + it * 256;
        int r = u >> 2, q = u & 3;
        cpasync16(sdst + r * T_STRIDE + q * 16, src + (size_t)r * ld + q * 8);
    }
}
__device__ __forceinline__ void chunk_ld(uint32_t sbase, int st,
                                         const __nv_bfloat16* Ah, const __nv_bfloat16* Al,
                                         const __nv_bfloat16* Bh, const __nv_bfloat16* Bl,
                                         int lda, int ldb, int k0, int tid) {
    const uint32_t s = sbase + st * STAGE_SZ;
    tile_ld(s,          Ah + k0, lda, tid);
    tile_ld(s + OFF_AL, Al + k0, lda, tid);
    tile_ld(s + OFF_BH, Bh + k0, ldb, tid);
    tile_ld(s + OFF_BL, Bl + k0, ldb, tid);
    cpcommit();
}
__device__ __forceinline__ void compute_chunk(uint32_t sb, int wm0, int wn0,
                                              int lane, float acc[2][8][4]) {
    const int rowoff = lane & 15;
    const int koff   = (lane >> 4) * 16;
    #pragma unroll
    for (int ks = 0; ks < 2; ks++) {
        const int kb = ks * 32 + koff;
        uint32_t ah[2][4], al[2][4], bh[8][2], bl[8][2];
        #pragma unroll
        for (int mi = 0; mi < 2; mi++) {
            ldsm4(ah[mi], sb + (uint32_t)(wm0 + mi * 16 + rowoff) * T_STRIDE + kb);
            ldsm4(al[mi], sb + OFF_AL + (uint32_t)(wm0 + mi * 16 + rowoff) * T_STRIDE + kb);
        }
        #pragma unroll
        for (int nf = 0; nf < 4; nf++) {
            uint32_t r4[4];
            ldsm4(r4, sb + OFF_BH + (uint32_t)(wn0 + nf * 16 + rowoff) * T_STRIDE + kb);
            bh[nf*2][0] = r4[0]; bh[nf*2+1][0] = r4[1];
            bh[nf*2][1] = r4[2]; bh[nf*2+1][1] = r4[3];
            ldsm4(r4, sb + OFF_BL + (uint32_t)(wn0 + nf * 16 + rowoff) * T_STRIDE + kb);
            bl[nf*2][0] = r4[0]; bl[nf*2+1][0] = r4[1];
            bl[nf*2][1] = r4[2]; bl[nf*2+1][1] = r4[3];
        }
        #pragma unroll
        for (int mi = 0; mi < 2; mi++)
            #pragma unroll
            for (int ni = 0; ni < 8; ni++)
                mma16816(acc[mi][ni], ah[mi], bh[ni]);
        #pragma unroll
        for (int mi = 0; mi < 2; mi++)
            #pragma unroll
            for (int ni = 0; ni < 8; ni++)
                mma16816(acc[mi][ni], al[mi], bh[ni]);
        #pragma unroll
        for (int mi = 0; mi < 2; mi++)
            #pragma unroll
            for (int ni = 0; ni < 8; ni++)
                mma16816(acc[mi][ni], ah[mi], bl[ni]);
    }
}
__device__ __forceinline__ void gemm_main(uint32_t sbase, int NK,
                                          const __nv_bfloat16* Ah, const __nv_bfloat16* Al,
                                          const __nv_bfloat16* Bh, const __nv_bfloat16* Bl,
                                          int lda, int ldb, int tid,
                                          int wm0, int wn0, float acc[2][8][4]) {
    const int lane = tid & 31;
    chunk_ld(sbase, 0, Ah, Al, Bh, Bl, lda, ldb, 0, tid);
    for (int kc = 0; kc < NK; kc++) {
        if (kc + 1 < NK) {
            chunk_ld(sbase, (kc + 1) & 1, Ah, Al, Bh, Bl, lda, ldb,
                     (kc + 1) * 32, tid);
            cpwait<1>();
        } else {
            cpwait<0>();
        }
        __syncthreads();
        compute_chunk(sbase + (kc & 1) * STAGE_SZ, wm0, wn0, lane, acc);
        __syncthreads();
    }
}

// ---------------- fp32 SIMT GEMM path (FMA pipe) ------------------------
// 128x128 tile, BK=8, 256 threads, 8x8 microtile. smem stride 132 floats.
#define F_STRIDE 132
__device__ __forceinline__ void gemm_f32(const float* A, const float* B,
                                         int lda, int ldb, int NK8,
                                         char* smc, int tid, float acc[8][8]) {
    float* As = (float*)smc;
    float* Bs = (float*)(smc + 8 * F_STRIDE * 4);
    const int r = tid >> 1, q4 = (tid & 1) * 4;
    const int ty = tid >> 4, tx = tid & 15;
    for (int kc = 0; kc < NK8; kc++) {
        const int k0 = kc * 8;
        float4 va = *(const float4*)(A + (size_t)r * lda + k0 + q4);
        float4 vb = *(const float4*)(B + (size_t)r * ldb + k0 + q4);
        __syncthreads();
        As[(q4+0)*F_STRIDE + r] = va.x; As[(q4+1)*F_STRIDE + r] = va.y;
        As[(q4+2)*F_STRIDE + r] = va.z; As[(q4+3)*F_STRIDE + r] = va.w;
        Bs[(q4+0)*F_STRIDE + r] = vb.x; Bs[(q4+1)*F_STRIDE + r] = vb.y;
        Bs[(q4+2)*F_STRIDE + r] = vb.z; Bs[(q4+3)*F_STRIDE + r] = vb.w;
        __syncthreads();
        #pragma unroll
        for (int kk = 0; kk < 8; kk++) {
            float4 a0 = *(const float4*)&As[kk*F_STRIDE + ty*8];
            float4 a1 = *(const float4*)&As[kk*F_STRIDE + ty*8 + 4];
            float4 b0 = *(const float4*)&Bs[kk*F_STRIDE + tx*8];
            float4 b1 = *(const float4*)&Bs[kk*F_STRIDE + tx*8 + 4];
            const float av[8] = {a0.x,a0.y,a0.z,a0.w,a1.x,a1.y,a1.z,a1.w};
            const float bv[8] = {b0.x,b0.y,b0.z,b0.w,b1.x,b1.y,b1.z,b1.w};
            #pragma unroll
            for (int i = 0; i < 8; i++)
                #pragma unroll
                for (int j = 0; j < 8; j++)
                    acc[i][j] = fmaf(av[i], bv[j], acc[i][j]);
        }
    }
}

// ---------------------------------------------------------------------------
// Kernel 0: split fp32 inputs into bf16 hi/lo arrays (single launch).
// ---------------------------------------------------------------------------
__global__ __launch_bounds__(256) void split_kernel(
    const float* __restrict__ x,  const float* __restrict__ Wq,
    const float* __restrict__ Wk, const float* __restrict__ Wv) {
    const size_t NX = (size_t)MROWS * CH;
    const size_t NW = (size_t)CH * CH;
    size_t i = ((size_t)blockIdx.x * 256 + threadIdx.x) * 4;

    const float* src;
    __nv_bfloat16 *hi, *lo;
    size_t off;
    if (i < NX)             { src = x;  hi = g_xh;         lo = g_xl;         off = i; }
    else if (i < NX + NW)   { src = Wq; hi = g_wh;         lo = g_wl;         off = i - NX; }
    else if (i < NX + 2*NW) { src = Wk; hi = g_wh + NW;    lo = g_wl + NW;    off = i - NX - NW; }
    else if (i < NX + 3*NW) { src = Wv; hi = g_wh + 2*NW;  lo = g_wl + 2*NW;  off = i - NX - 2*NW; }
    else return;

    float4 v = *(const float4*)(src + off);
    uint32_t l0, l1;
    uint32_t h0 = hilo_pack(v.x, v.y, l0);
    uint32_t h1 = hilo_pack(v.z, v.w, l1);
    *(uint32_t*)(hi + off)     = h0;
    *(uint32_t*)(hi + off + 2) = h1;
    *(uint32_t*)(lo + off)     = l0;
    *(uint32_t*)(lo + off + 2) = l1;
}

// ---------------------------------------------------------------------------
// Kernel 1: QKV (dual-path). grid (24, 64). bx&3==0 -> fp32 SIMT path.
// ---------------------------------------------------------------------------
__global__ __launch_bounds__(256, 2) void qkv_kernel(
    const float* __restrict__ x,  const float* __restrict__ Wq,
    const float* __restrict__ Wk, const float* __restrict__ Wv) {
    extern __shared__ char sm[];
    const int tid = threadIdx.x;
    const int mat = blockIdx.x >> 3;
    const int n0  = (blockIdx.x & 7) * 128;
    const int m0  = blockIdx.y * 128;

    if ((blockIdx.x & 3) == 0) {
        // ---- fp32 SIMT path (FMA pipe) ----
        const float* W = (mat == 0) ? Wq : (mat == 1) ? Wk : Wv;
        float acc[8][8] = {};
        gemm_f32(x + (size_t)m0 * CH, W + (size_t)n0 * CH, CH, CH,
                 CH / 8, sm, tid, acc);
        const int ty = tid >> 4, tx = tid & 15;
        #pragma unroll
        for (int i = 0; i < 8; i++) {
            int row = m0 + ty * 8 + i;
            if (mat < 2) {
                __nv_bfloat16* Hd = mat ? g_kh : g_qh;
                __nv_bfloat16* Ld = mat ? g_kl : g_ql;
                float* Ff = mat ? g_Kf : g_Qf;
                #pragma unroll
                for (int j = 0; j < 8; j += 2) {
                    int col = n0 + tx * 8 + j;
                    uint32_t lo;
                    uint32_t hiw = hilo_pack(acc[i][j], acc[i][j+1], lo);
                    *(uint32_t*)&Hd[(size_t)row * CH + col] = hiw;
                    *(uint32_t*)&Ld[(size_t)row * CH + col] = lo;
                    *(float2*)&Ff[(size_t)row * CH + col] =
                        make_float2(acc[i][j], acc[i][j+1]);
                }
            } else {
                int b = row >> 11, t = row & (SEQ - 1);
                #pragma unroll
                for (int j = 0; j < 8; j++) {
                    int col = n0 + tx * 8 + j;
                    float v = acc[i][j];
                    __nv_bfloat16 hh = __float2bfloat16(v);
                    size_t idx = ((size_t)b * CH + col) * SEQ + t;
                    g_vth[idx] = hh;
                    g_vtl[idx] = __float2bfloat16(v - __bfloat162float(hh));
                    g_Vtf[idx] = v;
                }
            }
        }
        return;
    }

    // ---- bf16 3-term tensor path ----
    const int wid = tid >> 5, lane = tid & 31;
    const int wm0 = (wid & 3) * 32, wn0 = (wid >> 2) * 64;
    const uint32_t sbase = su32(sm);

    const __nv_bfloat16* Ah = g_xh + (size_t)m0 * CH;
    const __nv_bfloat16* Al = g_xl + (size_t)m0 * CH;
    const __nv_bfloat16* Bh = g_wh + (size_t)mat * CH * CH + (size_t)n0 * CH;
    const __nv_bfloat16* Bl = g_wl + (size_t)mat * CH * CH + (size_t)n0 * CH;

    float acc[2][8][4] = {};
    gemm_main(sbase, CH / 32, Ah, Al, Bh, Bl, CH, CH, tid, wm0, wn0, acc);

    const int qrow = lane >> 2, qcol = (lane & 3) * 2;
    if (mat < 2) {
        __nv_bfloat16* Hd = mat ? g_kh : g_qh;
        __nv_bfloat16* Ld = mat ? g_kl : g_ql;
        float* Ff = mat ? g_Kf : g_Qf;
        #pragma unroll
        for (int mi = 0; mi < 2; mi++)
            #pragma unroll
            for (int ni = 0; ni < 8; ni++)
                #pragma unroll
                for (int h = 0; h < 2; h++) {
                    float v0 = acc[mi][ni][h*2+0], v1 = acc[mi][ni][h*2+1];
                    int row = m0 + wm0 + mi*16 + qrow + h*8;
                    int col = n0 + wn0 + ni*8 + qcol;
                    uint32_t lo;
                    uint32_t hiw = hilo_pack(v0, v1, lo);
                    *(uint32_t*)&Hd[(size_t)row * CH + col] = hiw;
                    *(uint32_t*)&Ld[(size_t)row * CH + col] = lo;
                    *(float2*)&Ff[(size_t)row * CH + col] = make_float2(v0, v1);
                }
    } else {
        #pragma unroll
        for (int mi = 0; mi < 2; mi++)
            #pragma unroll
            for (int ni = 0; ni < 8; ni++)
                #pragma unroll
                for (int h = 0; h < 2; h++) {
                    int row = m0 + wm0 + mi*16 + qrow + h*8;
                    int b = row >> 11, t = row & (SEQ - 1);
                    int col = n0 + wn0 + ni*8 + qcol;
                    #pragma unroll
                    for (int j = 0; j < 2; j++) {
                        float v = acc[mi][ni][h*2+j];
                        __nv_bfloat16 hh = __float2bfloat16(v);
                        size_t idx = ((size_t)b * CH + col + j) * SEQ + t;
                        g_vth[idx] = hh;
                        g_vtl[idx] = __float2bfloat16(v - __bfloat162float(hh));
                        g_Vtf[idx] = v;
                    }
                }
    }
}

// ---------------------------------------------------------------------------
// Kernel 2: scores (dual-path). 128x128 tiles, skip strictly-upper.
// ---------------------------------------------------------------------------
__global__ __launch_bounds__(256, 2) void scores_kernel() {
    if (blockIdx.x > blockIdx.y) return;
    extern __shared__ char sm[];
    const int tid = threadIdx.x;
    const int b  = blockIdx.z;
    const int s0 = blockIdx.x * 128;
    const int t0 = blockIdx.y * 128;
    const float scl = 0.03125f;   // 1/sqrt(1024)

    if ((blockIdx.x & 3) == 0) {
        float acc[8][8] = {};
        gemm_f32(g_Qf + (size_t)(b * SEQ + t0) * CH,
                 g_Kf + (size_t)(b * SEQ + s0) * CH, CH, CH,
                 CH / 8, sm, tid, acc);
        const int ty = tid >> 4, tx = tid & 15;
        #pragma unroll
        for (int i = 0; i < 8; i++) {
            int t = t0 + ty * 8 + i;
            #pragma unroll
            for (int j = 0; j < 8; j += 2) {
                int s = s0 + tx * 8 + j;
                *(float2*)&g_S[((size_t)b * SEQ + t) * SEQ + s] =
                    make_float2(acc[i][j] * scl, acc[i][j+1] * scl);
            }
        }
        return;
    }

    const int wid = tid >> 5, lane = tid & 31;
    const int wm0 = (wid & 3) * 32, wn0 = (wid >> 2) * 64;
    const uint32_t sbase = su32(sm);

    const size_t ar = (size_t)(b * SEQ + t0) * CH;
    const size_t br = (size_t)(b * SEQ + s0) * CH;

    float acc[2][8][4] = {};
    gemm_main(sbase, CH / 32, g_qh + ar, g_ql + ar, g_kh + br, g_kl + br,
              CH, CH, tid, wm0, wn0, acc);

    const int qrow = lane >> 2, qcol = (lane & 3) * 2;
    #pragma unroll
    for (int mi = 0; mi < 2; mi++)
        #pragma unroll
        for (int ni = 0; ni < 8; ni++)
            #pragma unroll
            for (int h = 0; h < 2; h++) {
                int t = t0 + wm0 + mi*16 + qrow + h*8;
                int s = s0 + wn0 + ni*8 + qcol;
                *(float2*)&g_S[((size_t)b * SEQ + t) * SEQ + s] =
                    make_float2(acc[mi][ni][h*2] * scl, acc[mi][ni][h*2+1] * scl);
            }
}

// ---------------------------------------------------------------------------
// Kernel 3: row softmax; writes P bf16 hi/lo AND fp32 P (in-place in g_S),
// zeros to the 128-tile boundary.
// ---------------------------------------------------------------------------
__global__ __launch_bounds__(256) void softmax_kernel() {
    const int t = blockIdx.x;
    const int b = blockIdx.y;
    const size_t rowb = ((size_t)b * SEQ + t) * SEQ;
    float* Srow = g_S + rowb;
    const int tid = threadIdx.x;
    const int len = ((t >> 7) + 1) << 7;

    float v[8];
    float m = -CUDART_INF_F;
    #pragma unroll
    for (int i = 0; i < 8; i++) {
        int s = tid + i * 256;
        v[i] = (s <= t) ? Srow[s] : -CUDART_INF_F;
        m = fmaxf(m, v[i]);
    }
    #pragma unroll
    for (int o = 16; o; o >>= 1) m = fmaxf(m, __shfl_xor_sync(~0u, m, o));
    __shared__ float smax[8], ssum[8];
    if ((tid & 31) == 0) smax[tid >> 5] = m;
    __syncthreads();
    m = smax[0];
    #pragma unroll
    for (int i = 1; i < 8; i++) m = fmaxf(m, smax[i]);

    float s = 0.f;
    #pragma unroll
    for (int i = 0; i < 8; i++) { v[i] = expf(v[i] - m); s += v[i]; }
    #pragma unroll
    for (int o = 16; o; o >>= 1) s += __shfl_xor_sync(~0u, s, o);
    if ((tid & 31) == 0) ssum[tid >> 5] = s;
    __syncthreads();
    s = 0.f;
    #pragma unroll
    for (int i = 0; i < 8; i++) s += ssum[i];
    const float inv = 1.0f / s;

    #pragma unroll
    for (int i = 0; i < 8; i++) {
        int sc = tid + i * 256;
        if (sc < len) {
            float p = v[i] * inv;
            __nv_bfloat16 h = __float2bfloat16(p);
            g_ph[rowb + sc] = h;
            g_pl[rowb + sc] = __float2bfloat16(p - __bfloat162float(h));
            Srow[sc] = p;
        }
    }
}

// ---------------------------------------------------------------------------
// Kernel 4: O = P V (dual-path). 128x128 tiles, K clipped at t0+128.
// ---------------------------------------------------------------------------
__global__ __launch_bounds__(256, 2) void pv_kernel(float* __restrict__ out) {
    extern __shared__ char sm[];
    const int tid = threadIdx.x;
    const int b  = blockIdx.z;
    const int c0 = blockIdx.x * 128;
    const int t0 = blockIdx.y * 128;

    if ((blockIdx.x & 3) == 0) {
        float acc[8][8] = {};
        gemm_f32(g_S   + ((size_t)b * SEQ + t0) * SEQ,
                 g_Vtf + ((size_t)b * CH  + c0) * SEQ, SEQ, SEQ,
                 (t0 + 128) / 8, sm, tid, acc);
        const int ty = tid >> 4, tx = tid & 15;
        #pragma unroll
        for (int i = 0; i < 8; i++) {
            int t = t0 + ty * 8 + i;
            #pragma unroll
            for (int j = 0; j < 8; j += 2) {
                int c = c0 + tx * 8 + j;
                *(float2*)&out[((size_t)b * SEQ + t) * CH + c] =
                    make_float2(acc[i][j], acc[i][j+1]);
            }
        }
        return;
    }

    const int wid = tid >> 5, lane = tid & 31;
    const int wm0 = (wid & 3) * 32, wn0 = (wid >> 2) * 64;
    const uint32_t sbase = su32(sm);

    const __nv_bfloat16* Ah = g_ph  + ((size_t)b * SEQ + t0) * SEQ;
    const __nv_bfloat16* Al = g_pl  + ((size_t)b * SEQ + t0) * SEQ;
    const __nv_bfloat16* Bh = g_vth + ((size_t)b * CH + c0) * SEQ;
    const __nv_bfloat16* Bl = g_vtl + ((size_t)b * CH + c0) * SEQ;

    float acc[2][8][4] = {};
    gemm_main(sbase, (t0 + 128) / 32, Ah, Al, Bh, Bl, SEQ, SEQ, tid,
              wm0, wn0, acc);

    const int qrow = lane >> 2, qcol = (lane & 3) * 2;
    #pragma unroll
    for (int mi = 0; mi < 2; mi++)
        #pragma unroll
        for (int ni = 0; ni < 8; ni++)
            #pragma unroll
            for (int h = 0; h < 2; h++) {
                int t = t0 + wm0 + mi*16 + qrow + h*8;
                int c = c0 + wn0 + ni*8 + qcol;
                *(float2*)&out[((size_t)b * SEQ + t) * CH + c] =
                    make_float2(acc[mi][ni][h*2], acc[mi][ni][h*2+1]);
            }
}

// ---------------------------------------------------------------------------
extern "C" void kernel_launch(void* const* d_in, const int* in_sizes, int n_in,
                              void* d_out, int out_size)
{
    const float* x  = (const float*)d_in[0];
    const float* Wq = (const float*)d_in[1];
    const float* Wk = (const float*)d_in[2];
    const float* Wv = (const float*)d_in[3];
    float* out = (float*)d_out;

    cudaFuncSetAttribute(qkv_kernel,
                         cudaFuncAttributeMaxDynamicSharedMemorySize, SMEM_TOT);
    cudaFuncSetAttribute(scores_kernel,
                         cudaFuncAttributeMaxDynamicSharedMemorySize, SMEM_TOT);
    cudaFuncSetAttribute(pv_kernel,
                         cudaFuncAttributeMaxDynamicSharedMemorySize, SMEM_TOT);

    const size_t n_split = (size_t)MROWS * CH + 3 * (size_t)CH * CH;
    split_kernel<<<(unsigned)(n_split / 1024), 256>>>(x, Wq, Wk, Wv);

    qkv_kernel<<<dim3(8 * 3, MROWS / 128), 256, SMEM_TOT>>>(x, Wq, Wk, Wv);
    scores_kernel<<<dim3(SEQ / 128, SEQ / 128, BATCH), 256, SMEM_TOT>>>();
    softmax_kernel<<<dim3(SEQ, BATCH), 256>>>();
    pv_kernel<<<dim3(CH / 128, SEQ / 128, BATCH), 256, SMEM_TOT>>>(out);
}

// round 12
// speedup vs baseline: 2.3785x; 1.7107x over previous
#include <cuda_runtime.h>
#include <cuda_bf16.h>
#include <math_constants.h>
#include <cstdint>

#define BATCH 4
#define SEQ   2048
#define CH    1024
#define MROWS (BATCH * SEQ)   // 8192

// ---------------- scratch (device globals; allocation-free) ----------------
static __device__ __nv_bfloat16 g_xh[(size_t)MROWS * CH];
static __device__ __nv_bfloat16 g_xl[(size_t)MROWS * CH];
static __device__ __nv_bfloat16 g_wh[(size_t)3 * CH * CH];
static __device__ __nv_bfloat16 g_wl[(size_t)3 * CH * CH];
static __device__ __nv_bfloat16 g_qh[(size_t)MROWS * CH];
static __device__ __nv_bfloat16 g_ql[(size_t)MROWS * CH];
static __device__ __nv_bfloat16 g_kh[(size_t)MROWS * CH];
static __device__ __nv_bfloat16 g_kl[(size_t)MROWS * CH];
static __device__ __nv_bfloat16 g_vth[(size_t)BATCH * CH * SEQ];  // V^T: [b][c][s]
static __device__ __nv_bfloat16 g_vtl[(size_t)BATCH * CH * SEQ];
static __device__ float         g_S [(size_t)BATCH * SEQ * SEQ];
static __device__ __nv_bfloat16 g_ph[(size_t)BATCH * SEQ * SEQ];
static __device__ __nv_bfloat16 g_pl[(size_t)BATCH * SEQ * SEQ];

// ---------------- baseline-PTX helpers ----------------
__device__ __forceinline__ uint32_t su32(const void* p) {
    uint32_t a;
    asm("{ .reg .u64 t; cvta.to.shared.u64 t, %1; cvt.u32.u64 %0, t; }"
        : "=r"(a) : "l"(p));
    return a;
}
__device__ __forceinline__ void cpasync16(uint32_t dst, const void* src) {
    asm volatile("cp.async.cg.shared.global [%0], [%1], 16;"
                 :: "r"(dst), "l"(src) : "memory");
}
__device__ __forceinline__ void cpcommit() {
    asm volatile("cp.async.commit_group;" ::: "memory");
}
template<int N> __device__ __forceinline__ void cpwait() {
    asm volatile("cp.async.wait_group %0;" :: "n"(N) : "memory");
}
__device__ __forceinline__ void ldsm4(uint32_t* r, uint32_t addr) {
    asm volatile("ldmatrix.sync.aligned.m8n8.x4.shared.b16 {%0,%1,%2,%3}, [%4];"
                 : "=r"(r[0]), "=r"(r[1]), "=r"(r[2]), "=r"(r[3]) : "r"(addr));
}
__device__ __forceinline__ void mma16816(float* d, const uint32_t* a,
                                         const uint32_t* b) {
    asm volatile(
        "mma.sync.aligned.m16n8k16.row.col.f32.bf16.bf16.f32 "
        "{%0,%1,%2,%3},{%4,%5,%6,%7},{%8,%9},{%0,%1,%2,%3};"
        : "+f"(d[0]), "+f"(d[1]), "+f"(d[2]), "+f"(d[3])
        : "r"(a[0]), "r"(a[1]), "r"(a[2]), "r"(a[3]), "r"(b[0]), "r"(b[1]));
}
__device__ __forceinline__ uint32_t pk(__nv_bfloat16 a, __nv_bfloat16 b) {
    uint16_t x = reinterpret_cast<uint16_t&>(a);
    uint16_t y = reinterpret_cast<uint16_t&>(b);
    return (uint32_t)x | ((uint32_t)y << 16);
}

// ---------------- smem tile geometry (R6 champion) ----------------
#define T_STRIDE 80
#define OFF_AL   10240
#define OFF_BH   20480
#define OFF_BL   30720
#define STAGE_SZ 40960
#define SMEM_TOT (2 * STAGE_SZ)

__device__ __forceinline__ void tile_ld(uint32_t sdst, const __nv_bfloat16* src,
                                        int ld, int tid) {
    #pragma unroll
    for (int it = 0; it < 2; it++) {
        int u = tid + it * 256;
        int r = u >> 2, q = u & 3;
        cpasync16(sdst + r * T_STRIDE + q * 16, src + (size_t)r * ld + q * 8);
    }
}
__device__ __forceinline__ void chunk_ld(uint32_t sbase, int st,
                                         const __nv_bfloat16* Ah, const __nv_bfloat16* Al,
                                         const __nv_bfloat16* Bh, const __nv_bfloat16* Bl,
                                         int lda, int ldb, int k0, int tid) {
    const uint32_t s = sbase + st * STAGE_SZ;
    tile_ld(s,          Ah + k0, lda, tid);
    tile_ld(s + OFF_AL, Al + k0, lda, tid);
    tile_ld(s + OFF_BH, Bh + k0, ldb, tid);
    tile_ld(s + OFF_BL, Bl + k0, ldb, tid);
    cpcommit();
}
__device__ __forceinline__ void compute_chunk(uint32_t sb, int wm0, int wn0,
                                              int lane, float acc[2][8][4]) {
    const int rowoff = lane & 15;
    const int koff   = (lane >> 4) * 16;
    #pragma unroll
    for (int ks = 0; ks < 2; ks++) {
        const int kb = ks * 32 + koff;
        uint32_t ah[2][4], al[2][4], bh[8][2], bl[8][2];
        #pragma unroll
        for (int mi = 0; mi < 2; mi++) {
            ldsm4(ah[mi], sb + (uint32_t)(wm0 + mi * 16 + rowoff) * T_STRIDE + kb);
            ldsm4(al[mi], sb + OFF_AL + (uint32_t)(wm0 + mi * 16 + rowoff) * T_STRIDE + kb);
        }
        #pragma unroll
        for (int nf = 0; nf < 4; nf++) {
            uint32_t r4[4];
            ldsm4(r4, sb + OFF_BH + (uint32_t)(wn0 + nf * 16 + rowoff) * T_STRIDE + kb);
            bh[nf*2][0] = r4[0]; bh[nf*2+1][0] = r4[1];
            bh[nf*2][1] = r4[2]; bh[nf*2+1][1] = r4[3];
            ldsm4(r4, sb + OFF_BL + (uint32_t)(wn0 + nf * 16 + rowoff) * T_STRIDE + kb);
            bl[nf*2][0] = r4[0]; bl[nf*2+1][0] = r4[1];
            bl[nf*2][1] = r4[2]; bl[nf*2+1][1] = r4[3];
        }
        #pragma unroll
        for (int mi = 0; mi < 2; mi++)
            #pragma unroll
            for (int ni = 0; ni < 8; ni++)
                mma16816(acc[mi][ni], ah[mi], bh[ni]);
        #pragma unroll
        for (int mi = 0; mi < 2; mi++)
            #pragma unroll
            for (int ni = 0; ni < 8; ni++)
                mma16816(acc[mi][ni], al[mi], bh[ni]);
        #pragma unroll
        for (int mi = 0; mi < 2; mi++)
            #pragma unroll
            for (int ni = 0; ni < 8; ni++)
                mma16816(acc[mi][ni], ah[mi], bl[ni]);
    }
}
__device__ __forceinline__ void gemm_main(uint32_t sbase, int NK,
                                          const __nv_bfloat16* Ah, const __nv_bfloat16* Al,
                                          const __nv_bfloat16* Bh, const __nv_bfloat16* Bl,
                                          int lda, int ldb, int tid,
                                          int wm0, int wn0, float acc[2][8][4]) {
    const int lane = tid & 31;
    chunk_ld(sbase, 0, Ah, Al, Bh, Bl, lda, ldb, 0, tid);
    for (int kc = 0; kc < NK; kc++) {
        if (kc + 1 < NK) {
            chunk_ld(sbase, (kc + 1) & 1, Ah, Al, Bh, Bl, lda, ldb,
                     (kc + 1) * 32, tid);
            cpwait<1>();
        } else {
            cpwait<0>();
        }
        __syncthreads();
        compute_chunk(sbase + (kc & 1) * STAGE_SZ, wm0, wn0, lane, acc);
        __syncthreads();
    }
}

// ---------------------------------------------------------------------------
// Kernel 0: split fp32 inputs into bf16 hi/lo arrays (single launch).
// ---------------------------------------------------------------------------
__global__ __launch_bounds__(256) void split_kernel(
    const float* __restrict__ x,  const float* __restrict__ Wq,
    const float* __restrict__ Wk, const float* __restrict__ Wv) {
    const size_t NX = (size_t)MROWS * CH;
    const size_t NW = (size_t)CH * CH;
    size_t i = ((size_t)blockIdx.x * 256 + threadIdx.x) * 4;

    const float* src;
    __nv_bfloat16 *hi, *lo;
    size_t off;
    if (i < NX)             { src = x;  hi = g_xh;         lo = g_xl;         off = i; }
    else if (i < NX + NW)   { src = Wq; hi = g_wh;         lo = g_wl;         off = i - NX; }
    else if (i < NX + 2*NW) { src = Wk; hi = g_wh + NW;    lo = g_wl + NW;    off = i - NX - NW; }
    else if (i < NX + 3*NW) { src = Wv; hi = g_wh + 2*NW;  lo = g_wl + 2*NW;  off = i - NX - 2*NW; }
    else return;

    float4 v = *(const float4*)(src + off);
    __nv_bfloat16 h0 = __float2bfloat16(v.x), h1 = __float2bfloat16(v.y);
    __nv_bfloat16 h2 = __float2bfloat16(v.z), h3 = __float2bfloat16(v.w);
    *(uint32_t*)(hi + off)     = pk(h0, h1);
    *(uint32_t*)(hi + off + 2) = pk(h2, h3);
    *(uint32_t*)(lo + off)     = pk(__float2bfloat16(v.x - __bfloat162float(h0)),
                                    __float2bfloat16(v.y - __bfloat162float(h1)));
    *(uint32_t*)(lo + off + 2) = pk(__float2bfloat16(v.z - __bfloat162float(h2)),
                                    __float2bfloat16(v.w - __bfloat162float(h3)));
}

// ---------------------------------------------------------------------------
// Kernel 1: QKV, persistent. Work w in [0,1536): mat = w>>9,
// n0 = ((w>>6)&7)*128, m0 = (w&63)*128.
// ---------------------------------------------------------------------------
#define QKV_NWORK 1536
__global__ __launch_bounds__(256, 2) void qkv_kernel() {
    extern __shared__ char sm[];
    const int tid = threadIdx.x, wid = tid >> 5, lane = tid & 31;
    const int wm0 = (wid & 3) * 32, wn0 = (wid >> 2) * 64;
    const uint32_t sbase = su32(sm);
    const int qrow = lane >> 2, qcol = (lane & 3) * 2;

    for (int w = blockIdx.x; w < QKV_NWORK; w += gridDim.x) {
        const int mat = w >> 9;
        const int n0  = ((w >> 6) & 7) * 128;
        const int m0  = (w & 63) * 128;

        const __nv_bfloat16* Ah = g_xh + (size_t)m0 * CH;
        const __nv_bfloat16* Al = g_xl + (size_t)m0 * CH;
        const __nv_bfloat16* Bh = g_wh + (size_t)mat * CH * CH + (size_t)n0 * CH;
        const __nv_bfloat16* Bl = g_wl + (size_t)mat * CH * CH + (size_t)n0 * CH;

        float acc[2][8][4] = {};
        gemm_main(sbase, CH / 32, Ah, Al, Bh, Bl, CH, CH, tid, wm0, wn0, acc);

        if (mat < 2) {
            __nv_bfloat16* Hd = mat ? g_kh : g_qh;
            __nv_bfloat16* Ld = mat ? g_kl : g_ql;
            #pragma unroll
            for (int mi = 0; mi < 2; mi++)
                #pragma unroll
                for (int ni = 0; ni < 8; ni++)
                    #pragma unroll
                    for (int h = 0; h < 2; h++) {
                        float v0 = acc[mi][ni][h*2+0], v1 = acc[mi][ni][h*2+1];
                        int row = m0 + wm0 + mi*16 + qrow + h*8;
                        int col = n0 + wn0 + ni*8 + qcol;
                        __nv_bfloat16 h0 = __float2bfloat16(v0);
                        __nv_bfloat16 h1 = __float2bfloat16(v1);
                        *(uint32_t*)&Hd[(size_t)row * CH + col] = pk(h0, h1);
                        *(uint32_t*)&Ld[(size_t)row * CH + col] =
                            pk(__float2bfloat16(v0 - __bfloat162float(h0)),
                               __float2bfloat16(v1 - __bfloat162float(h1)));
                    }
        } else {
            #pragma unroll
            for (int mi = 0; mi < 2; mi++)
                #pragma unroll
                for (int ni = 0; ni < 8; ni++)
                    #pragma unroll
                    for (int h = 0; h < 2; h++) {
                        int row = m0 + wm0 + mi*16 + qrow + h*8;   // token
                        int b = row >> 11, t = row & (SEQ - 1);
                        int col = n0 + wn0 + ni*8 + qcol;          // channel
                        #pragma unroll
                        for (int j = 0; j < 2; j++) {
                            float v = acc[mi][ni][h*2+j];
                            __nv_bfloat16 hh = __float2bfloat16(v);
                            size_t idx = ((size_t)b * CH + col + j) * SEQ + t;
                            g_vth[idx] = hh;
                            g_vtl[idx] = __float2bfloat16(v - __bfloat162float(hh));
                        }
                    }
        }
        __syncthreads();
    }
}

// ---------------------------------------------------------------------------
// Kernel 2: scores, persistent over enumerated lower-triangle tiles.
// 136 tiles per batch (ti*(ti+1)/2 + si), 544 total.
// ---------------------------------------------------------------------------
#define SC_PERB  136
#define SC_NWORK (SC_PERB * BATCH)
__global__ __launch_bounds__(256, 2) void scores_kernel() {
    extern __shared__ char sm[];
    const int tid = threadIdx.x, wid = tid >> 5, lane = tid & 31;
    const int wm0 = (wid & 3) * 32, wn0 = (wid >> 2) * 64;
    const uint32_t sbase = su32(sm);
    const int qrow = lane >> 2, qcol = (lane & 3) * 2;
    const float scl = 0.03125f;

    for (int w = blockIdx.x; w < SC_NWORK; w += gridDim.x) {
        const int b = w / SC_PERB;
        const int r = w - b * SC_PERB;
        int ti = (int)((sqrtf(8.0f * r + 1.0f) - 1.0f) * 0.5f);
        while ((ti + 1) * (ti + 2) / 2 <= r) ti++;
        while (ti * (ti + 1) / 2 > r) ti--;
        const int si = r - ti * (ti + 1) / 2;
        const int t0 = ti * 128, s0 = si * 128;

        const size_t ar = (size_t)(b * SEQ + t0) * CH;
        const size_t br = (size_t)(b * SEQ + s0) * CH;

        float acc[2][8][4] = {};
        gemm_main(sbase, CH / 32, g_qh + ar, g_ql + ar, g_kh + br, g_kl + br,
                  CH, CH, tid, wm0, wn0, acc);

        #pragma unroll
        for (int mi = 0; mi < 2; mi++)
            #pragma unroll
            for (int ni = 0; ni < 8; ni++)
                #pragma unroll
                for (int h = 0; h < 2; h++) {
                    int t = t0 + wm0 + mi*16 + qrow + h*8;
                    int s = s0 + wn0 + ni*8 + qcol;
                    *(float2*)&g_S[((size_t)b * SEQ + t) * SEQ + s] =
                        make_float2(acc[mi][ni][h*2] * scl, acc[mi][ni][h*2+1] * scl);
                }
        __syncthreads();
    }
}

// ---------------------------------------------------------------------------
// Kernel 3: row softmax; writes P bf16 hi/lo, zeros to 128-tile boundary.
// ---------------------------------------------------------------------------
__global__ __launch_bounds__(256) void softmax_kernel() {
    const int t = blockIdx.x;
    const int b = blockIdx.y;
    const size_t rowb = ((size_t)b * SEQ + t) * SEQ;
    const float* Srow = g_S + rowb;
    const int tid = threadIdx.x;
    const int len = ((t >> 7) + 1) << 7;

    float v[8];
    float m = -CUDART_INF_F;
    #pragma unroll
    for (int i = 0; i < 8; i++) {
        int s = tid + i * 256;
        v[i] = (s <= t) ? Srow[s] : -CUDART_INF_F;
        m = fmaxf(m, v[i]);
    }
    #pragma unroll
    for (int o = 16; o; o >>= 1) m = fmaxf(m, __shfl_xor_sync(~0u, m, o));
    __shared__ float smax[8], ssum[8];
    if ((tid & 31) == 0) smax[tid >> 5] = m;
    __syncthreads();
    m = smax[0];
    #pragma unroll
    for (int i = 1; i < 8; i++) m = fmaxf(m, smax[i]);

    float s = 0.f;
    #pragma unroll
    for (int i = 0; i < 8; i++) { v[i] = expf(v[i] - m); s += v[i]; }
    #pragma unroll
    for (int o = 16; o; o >>= 1) s += __shfl_xor_sync(~0u, s, o);
    if ((tid & 31) == 0) ssum[tid >> 5] = s;
    __syncthreads();
    s = 0.f;
    #pragma unroll
    for (int i = 0; i < 8; i++) s += ssum[i];
    const float inv = 1.0f / s;

    #pragma unroll
    for (int i = 0; i < 8; i++) {
        int sc = tid + i * 256;
        if (sc < len) {
            float p = v[i] * inv;
            __nv_bfloat16 h = __float2bfloat16(p);
            g_ph[rowb + sc] = h;
            g_pl[rowb + sc] = __float2bfloat16(p - __bfloat162float(h));
        }
    }
}

// ---------------------------------------------------------------------------
// Kernel 4: O = P V, persistent; descending-t0 (LPT) order.
// Work w in [0,512): ti = 15 - (w>>5)  [largest K first],
// c0 = ((w>>2)&7)*128, b = w&3.   (16 ti x 8 c x 4 b = 512)
// ---------------------------------------------------------------------------
#define PV_NWORK 512
__global__ __launch_bounds__(256, 2) void pv_kernel(float* __restrict__ out) {
    extern __shared__ char sm[];
    const int tid = threadIdx.x, wid = tid >> 5, lane = tid & 31;
    const int wm0 = (wid & 3) * 32, wn0 = (wid >> 2) * 64;
    const uint32_t sbase = su32(sm);
    const int qrow = lane >> 2, qcol = (lane & 3) * 2;

    for (int w = blockIdx.x; w < PV_NWORK; w += gridDim.x) {
        const int ti = 15 - (w >> 5);
        const int c0 = ((w >> 2) & 7) * 128;
        const int b  = w & 3;
        const int t0 = ti * 128;

        const __nv_bfloat16* Ah = g_ph  + ((size_t)b * SEQ + t0) * SEQ;
        const __nv_bfloat16* Al = g_pl  + ((size_t)b * SEQ + t0) * SEQ;
        const __nv_bfloat16* Bh = g_vth + ((size_t)b * CH + c0) * SEQ;
        const __nv_bfloat16* Bl = g_vtl + ((size_t)b * CH + c0) * SEQ;

        float acc[2][8][4] = {};
        gemm_main(sbase, (t0 + 128) / 32, Ah, Al, Bh, Bl, SEQ, SEQ, tid,
                  wm0, wn0, acc);

        #pragma unroll
        for (int mi = 0; mi < 2; mi++)
            #pragma unroll
            for (int ni = 0; ni < 8; ni++)
                #pragma unroll
                for (int h = 0; h < 2; h++) {
                    int t = t0 + wm0 + mi*16 + qrow + h*8;
                    int c = c0 + wn0 + ni*8 + qcol;
                    *(float2*)&out[((size_t)b * SEQ + t) * CH + c] =
                        make_float2(acc[mi][ni][h*2], acc[mi][ni][h*2+1]);
                }
        __syncthreads();
    }
}

// ---------------------------------------------------------------------------
extern "C" void kernel_launch(void* const* d_in, const int* in_sizes, int n_in,
                              void* d_out, int out_size)
{
    const float* x  = (const float*)d_in[0];
    const float* Wq = (const float*)d_in[1];
    const float* Wk = (const float*)d_in[2];
    const float* Wv = (const float*)d_in[3];
    float* out = (float*)d_out;

    cudaFuncSetAttribute(qkv_kernel,
                         cudaFuncAttributeMaxDynamicSharedMemorySize, SMEM_TOT);
    cudaFuncSetAttribute(scores_kernel,
                         cudaFuncAttributeMaxDynamicSharedMemorySize, SMEM_TOT);
    cudaFuncSetAttribute(pv_kernel,
                         cudaFuncAttributeMaxDynamicSharedMemorySize, SMEM_TOT);

    int nsm = 148;
    cudaDeviceGetAttribute(&nsm, cudaDevAttrMultiProcessorCount, 0);
    const unsigned pgrid = (unsigned)(2 * nsm);   // persistent grid: 2 CTAs/SM

    const size_t n_split = (size_t)MROWS * CH + 3 * (size_t)CH * CH;
    split_kernel<<<(unsigned)(n_split / 1024), 256>>>(x, Wq, Wk, Wv);

    qkv_kernel<<<pgrid, 256, SMEM_TOT>>>();
    scores_kernel<<<pgrid, 256, SMEM_TOT>>>();
    softmax_kernel<<<dim3(SEQ, BATCH), 256>>>();
    pv_kernel<<<pgrid, 256, SMEM_TOT>>>(out);
}

// round 14
// speedup vs baseline: 3.4335x; 1.4435x over previous
#include <cuda_runtime.h>
#include <cuda_fp16.h>
#include <math_constants.h>
#include <cstdint>

#define BATCH 4
#define SEQ   2048
#define CH    1024
#define MROWS (BATCH * SEQ)   // 8192

// ---------------- scratch (device globals; allocation-free) ----------------
static __device__ __half g_xh[(size_t)MROWS * CH];                // x hi only
static __device__ __half g_wh[(size_t)3 * CH * CH];
static __device__ __half g_wl[(size_t)3 * CH * CH];
static __device__ __half g_qh[(size_t)MROWS * CH];                // Q hi only
static __device__ __half g_kh[(size_t)MROWS * CH];
static __device__ __half g_kl[(size_t)MROWS * CH];
static __device__ __half g_vth[(size_t)BATCH * CH * SEQ];         // V^T hi
static __device__ __half g_vtl[(size_t)BATCH * CH * SEQ];         // V^T lo
static __device__ float  g_S [(size_t)BATCH * SEQ * SEQ];
static __device__ __half g_ph[(size_t)BATCH * SEQ * SEQ];         // P hi only

// ---------------- baseline-PTX helpers ----------------
__device__ __forceinline__ uint32_t su32(const void* p) {
    uint32_t a;
    asm("{ .reg .u64 t; cvta.to.shared.u64 t, %1; cvt.u32.u64 %0, t; }"
        : "=r"(a) : "l"(p));
    return a;
}
__device__ __forceinline__ void cpasync16(uint32_t dst, const void* src) {
    asm volatile("cp.async.cg.shared.global [%0], [%1], 16;"
                 :: "r"(dst), "l"(src) : "memory");
}
__device__ __forceinline__ void cpcommit() {
    asm volatile("cp.async.commit_group;" ::: "memory");
}
template<int N> __device__ __forceinline__ void cpwait() {
    asm volatile("cp.async.wait_group %0;" :: "n"(N) : "memory");
}
__device__ __forceinline__ void ldsm4(uint32_t* r, uint32_t addr) {
    asm volatile("ldmatrix.sync.aligned.m8n8.x4.shared.b16 {%0,%1,%2,%3}, [%4];"
                 : "=r"(r[0]), "=r"(r[1]), "=r"(r[2]), "=r"(r[3]) : "r"(addr));
}
__device__ __forceinline__ void mma16816(float* d, const uint32_t* a,
                                         const uint32_t* b) {
    asm volatile(
        "mma.sync.aligned.m16n8k16.row.col.f32.f16.f16.f32 "
        "{%0,%1,%2,%3},{%4,%5,%6,%7},{%8,%9},{%0,%1,%2,%3};"
        : "+f"(d[0]), "+f"(d[1]), "+f"(d[2]), "+f"(d[3])
        : "r"(a[0]), "r"(a[1]), "r"(a[2]), "r"(a[3]), "r"(b[0]), "r"(b[1]));
}
__device__ __forceinline__ uint32_t pk(__half a, __half b) {
    uint16_t x = reinterpret_cast<uint16_t&>(a);
    uint16_t y = reinterpret_cast<uint16_t&>(b);
    return (uint32_t)x | ((uint32_t)y << 16);
}

// ---------------- smem tile geometry ----------------
// Tiles: 128 rows x 32 halves (64 B data), padded stride 80 B.
// Stage: A 0, Bh 10240, Bl 20480. Stage size 30720. 2 stages = 61440 B.
#define T_STRIDE 80
#define OFF_BH   10240
#define OFF_BL   20480
#define STAGE_SZ 30720
#define SMEM_TOT (2 * STAGE_SZ)

__device__ __forceinline__ void tile_ld(uint32_t sdst, const __half* src,
                                        int ld, int tid) {
    #pragma unroll
    for (int it = 0; it < 2; it++) {
        int u = tid + it * 256;
        int r = u >> 2, q = u & 3;
        cpasync16(sdst + r * T_STRIDE + q * 16, src + (size_t)r * ld + q * 8);
    }
}
__device__ __forceinline__ void chunk_ld(uint32_t sbase, int st,
                                         const __half* A,
                                         const __half* Bh, const __half* Bl,
                                         int lda, int ldb, int k0, int tid) {
    const uint32_t s = sbase + st * STAGE_SZ;
    tile_ld(s,          A  + k0, lda, tid);
    tile_ld(s + OFF_BH, Bh + k0, ldb, tid);
    tile_ld(s + OFF_BL, Bl + k0, ldb, tid);
    cpcommit();
}
// one 128x128 x k32 chunk; warp tile 32x64; 2-term: Ah*Bh + Ah*Bl.
__device__ __forceinline__ void compute_chunk(uint32_t sb, int wm0, int wn0,
                                              int lane, float acc[2][8][4]) {
    const int rowoff = lane & 15;
    const int koff   = (lane >> 4) * 16;
    #pragma unroll
    for (int ks = 0; ks < 2; ks++) {
        const int kb = ks * 32 + koff;
        uint32_t ah[2][4], bh[8][2], bl[8][2];
        #pragma unroll
        for (int mi = 0; mi < 2; mi++)
            ldsm4(ah[mi], sb + (uint32_t)(wm0 + mi * 16 + rowoff) * T_STRIDE + kb);
        #pragma unroll
        for (int nf = 0; nf < 4; nf++) {
            uint32_t r4[4];
            ldsm4(r4, sb + OFF_BH + (uint32_t)(wn0 + nf * 16 + rowoff) * T_STRIDE + kb);
            bh[nf*2][0] = r4[0]; bh[nf*2+1][0] = r4[1];
            bh[nf*2][1] = r4[2]; bh[nf*2+1][1] = r4[3];
            ldsm4(r4, sb + OFF_BL + (uint32_t)(wn0 + nf * 16 + rowoff) * T_STRIDE + kb);
            bl[nf*2][0] = r4[0]; bl[nf*2+1][0] = r4[1];
            bl[nf*2][1] = r4[2]; bl[nf*2+1][1] = r4[3];
        }
        #pragma unroll
        for (int mi = 0; mi < 2; mi++)
            #pragma unroll
            for (int ni = 0; ni < 8; ni++)
                mma16816(acc[mi][ni], ah[mi], bh[ni]);
        #pragma unroll
        for (int mi = 0; mi < 2; mi++)
            #pragma unroll
            for (int ni = 0; ni < 8; ni++)
                mma16816(acc[mi][ni], ah[mi], bl[ni]);
    }
}
__device__ __forceinline__ void gemm_main(uint32_t sbase, int NK,
                                          const __half* A,
                                          const __half* Bh, const __half* Bl,
                                          int lda, int ldb, int tid,
                                          int wm0, int wn0, float acc[2][8][4]) {
    const int lane = tid & 31;
    chunk_ld(sbase, 0, A, Bh, Bl, lda, ldb, 0, tid);
    for (int kc = 0; kc < NK; kc++) {
        if (kc + 1 < NK) {
            chunk_ld(sbase, (kc + 1) & 1, A, Bh, Bl, lda, ldb,
                     (kc + 1) * 32, tid);
            cpwait<1>();
        } else {
            cpwait<0>();
        }
        __syncthreads();
        compute_chunk(sbase + (kc & 1) * STAGE_SZ, wm0, wn0, lane, acc);
        __syncthreads();
    }
}

// ---------------------------------------------------------------------------
// Kernel 0: x -> fp16 hi only; W -> fp16 hi+lo. Single launch.
// ---------------------------------------------------------------------------
__global__ __launch_bounds__(256) void split_kernel(
    const float* __restrict__ x,  const float* __restrict__ Wq,
    const float* __restrict__ Wk, const float* __restrict__ Wv) {
    const size_t NX = (size_t)MROWS * CH;
    const size_t NW = (size_t)CH * CH;
    size_t i = ((size_t)blockIdx.x * 256 + threadIdx.x) * 4;

    if (i < NX) {
        float4 v = *(const float4*)(x + i);
        *(uint32_t*)(g_xh + i)     = pk(__float2half(v.x), __float2half(v.y));
        *(uint32_t*)(g_xh + i + 2) = pk(__float2half(v.z), __float2half(v.w));
        return;
    }
    const float* src; size_t off;
    if (i < NX + NW)        { src = Wq; off = i - NX; }
    else if (i < NX + 2*NW) { src = Wk; off = i - NX; }
    else if (i < NX + 3*NW) { src = Wv; off = i - NX; }
    else return;
    size_t loc = (i < NX + NW) ? off : (i < NX + 2*NW) ? off - NW : off - 2*NW;

    float4 v = *(const float4*)(src + loc);
    __half h0 = __float2half(v.x), h1 = __float2half(v.y);
    __half h2 = __float2half(v.z), h3 = __float2half(v.w);
    *(uint32_t*)(g_wh + off)     = pk(h0, h1);
    *(uint32_t*)(g_wh + off + 2) = pk(h2, h3);
    *(uint32_t*)(g_wl + off)     = pk(__float2half(v.x - __half2float(h0)),
                                      __float2half(v.y - __half2float(h1)));
    *(uint32_t*)(g_wl + off + 2) = pk(__float2half(v.z - __half2float(h2)),
                                      __float2half(v.w - __half2float(h3)));
}

// ---------------------------------------------------------------------------
// Kernel 1: QKV = xh * (Wh + Wl). grid (8*3, 64).
// Q -> hi only; K -> hi+lo; V -> transposed hi+lo.
// ---------------------------------------------------------------------------
__global__ __launch_bounds__(256, 2) void qkv_kernel() {
    extern __shared__ char sm[];
    const int tid = threadIdx.x, wid = tid >> 5, lane = tid & 31;
    const int mat = blockIdx.x >> 3;
    const int n0  = (blockIdx.x & 7) * 128;
    const int m0  = blockIdx.y * 128;
    const int wm0 = (wid & 3) * 32, wn0 = (wid >> 2) * 64;
    const uint32_t sbase = su32(sm);

    const __half* A  = g_xh + (size_t)m0 * CH;
    const __half* Bh = g_wh + (size_t)mat * CH * CH + (size_t)n0 * CH;
    const __half* Bl = g_wl + (size_t)mat * CH * CH + (size_t)n0 * CH;

    float acc[2][8][4] = {};
    gemm_main(sbase, CH / 32, A, Bh, Bl, CH, CH, tid, wm0, wn0, acc);

    const int qrow = lane >> 2, qcol = (lane & 3) * 2;
    if (mat == 0) {
        #pragma unroll
        for (int mi = 0; mi < 2; mi++)
            #pragma unroll
            for (int ni = 0; ni < 8; ni++)
                #pragma unroll
                for (int h = 0; h < 2; h++) {
                    int row = m0 + wm0 + mi*16 + qrow + h*8;
                    int col = n0 + wn0 + ni*8 + qcol;
                    *(uint32_t*)&g_qh[(size_t)row * CH + col] =
                        pk(__float2half(acc[mi][ni][h*2]),
                           __float2half(acc[mi][ni][h*2+1]));
                }
    } else if (mat == 1) {
        #pragma unroll
        for (int mi = 0; mi < 2; mi++)
            #pragma unroll
            for (int ni = 0; ni < 8; ni++)
                #pragma unroll
                for (int h = 0; h < 2; h++) {
                    float v0 = acc[mi][ni][h*2+0], v1 = acc[mi][ni][h*2+1];
                    int row = m0 + wm0 + mi*16 + qrow + h*8;
                    int col = n0 + wn0 + ni*8 + qcol;
                    __half h0 = __float2half(v0);
                    __half h1 = __float2half(v1);
                    *(uint32_t*)&g_kh[(size_t)row * CH + col] = pk(h0, h1);
                    *(uint32_t*)&g_kl[(size_t)row * CH + col] =
                        pk(__float2half(v0 - __half2float(h0)),
                           __float2half(v1 - __half2float(h1)));
                }
    } else {
        #pragma unroll
        for (int mi = 0; mi < 2; mi++)
            #pragma unroll
            for (int ni = 0; ni < 8; ni++)
                #pragma unroll
                for (int h = 0; h < 2; h++) {
                    int row = m0 + wm0 + mi*16 + qrow + h*8;   // token
                    int b = row >> 11, t = row & (SEQ - 1);
                    int col = n0 + wn0 + ni*8 + qcol;          // channel
                    #pragma unroll
                    for (int j = 0; j < 2; j++) {
                        float v = acc[mi][ni][h*2+j];
                        __half hh = __float2half(v);
                        size_t idx = ((size_t)b * CH + col + j) * SEQ + t;
                        g_vth[idx] = hh;
                        g_vtl[idx] = __float2half(v - __half2float(hh));
                    }
                }
    }
}

// ---------------------------------------------------------------------------
// Kernel 2: scores = (1/32) * Qh * (Kh + Kl). Skip strictly-upper tiles.
// ---------------------------------------------------------------------------
__global__ __launch_bounds__(256, 2) void scores_kernel() {
    if (blockIdx.x > blockIdx.y) return;
    extern __shared__ char sm[];
    const int tid = threadIdx.x, wid = tid >> 5, lane = tid & 31;
    const int b  = blockIdx.z;
    const int s0 = blockIdx.x * 128;
    const int t0 = blockIdx.y * 128;
    const int wm0 = (wid & 3) * 32, wn0 = (wid >> 2) * 64;
    const uint32_t sbase = su32(sm);

    const size_t ar = (size_t)(b * SEQ + t0) * CH;
    const size_t br = (size_t)(b * SEQ + s0) * CH;

    float acc[2][8][4] = {};
    gemm_main(sbase, CH / 32, g_qh + ar, g_kh + br, g_kl + br,
              CH, CH, tid, wm0, wn0, acc);

    const int qrow = lane >> 2, qcol = (lane & 3) * 2;
    const float scl = 0.03125f;
    #pragma unroll
    for (int mi = 0; mi < 2; mi++)
        #pragma unroll
        for (int ni = 0; ni < 8; ni++)
            #pragma unroll
            for (int h = 0; h < 2; h++) {
                int t = t0 + wm0 + mi*16 + qrow + h*8;
                int s = s0 + wn0 + ni*8 + qcol;
                *(float2*)&g_S[((size_t)b * SEQ + t) * SEQ + s] =
                    make_float2(acc[mi][ni][h*2] * scl, acc[mi][ni][h*2+1] * scl);
            }
}

// ---------------------------------------------------------------------------
// Kernel 3: row softmax; writes P fp16 hi only, zeros to 128-tile boundary.
// ---------------------------------------------------------------------------
__global__ __launch_bounds__(256) void softmax_kernel() {
    const int t = blockIdx.x;
    const int b = blockIdx.y;
    const size_t rowb = ((size_t)b * SEQ + t) * SEQ;
    const float* Srow = g_S + rowb;
    const int tid = threadIdx.x;
    const int len = ((t >> 7) + 1) << 7;

    float v[8];
    float m = -CUDART_INF_F;
    #pragma unroll
    for (int i = 0; i < 8; i++) {
        int s = tid + i * 256;
        v[i] = (s <= t) ? Srow[s] : -CUDART_INF_F;
        m = fmaxf(m, v[i]);
    }
    #pragma unroll
    for (int o = 16; o; o >>= 1) m = fmaxf(m, __shfl_xor_sync(~0u, m, o));
    __shared__ float smax[8], ssum[8];
    if ((tid & 31) == 0) smax[tid >> 5] = m;
    __syncthreads();
    m = smax[0];
    #pragma unroll
    for (int i = 1; i < 8; i++) m = fmaxf(m, smax[i]);

    float s = 0.f;
    #pragma unroll
    for (int i = 0; i < 8; i++) { v[i] = expf(v[i] - m); s += v[i]; }
    #pragma unroll
    for (int o = 16; o; o >>= 1) s += __shfl_xor_sync(~0u, s, o);
    if ((tid & 31) == 0) ssum[tid >> 5] = s;
    __syncthreads();
    s = 0.f;
    #pragma unroll
    for (int i = 0; i < 8; i++) s += ssum[i];
    const float inv = 1.0f / s;

    #pragma unroll
    for (int i = 0; i < 8; i++) {
        int sc = tid + i * 256;
        if (sc < len) g_ph[rowb + sc] = __float2half(v[i] * inv);
    }
}

// ---------------------------------------------------------------------------
// Kernel 4: O = Ph * (Vh + Vl). K clipped at t0+128.
// ---------------------------------------------------------------------------
__global__ __launch_bounds__(256, 2) void pv_kernel(float* __restrict__ out) {
    extern __shared__ char sm[];
    const int tid = threadIdx.x, wid = tid >> 5, lane = tid & 31;
    const int b  = blockIdx.z;
    const int c0 = blockIdx.x * 128;
    const int t0 = blockIdx.y * 128;
    const int wm0 = (wid & 3) * 32, wn0 = (wid >> 2) * 64;
    const uint32_t sbase = su32(sm);

    const __half* A  = g_ph  + ((size_t)b * SEQ + t0) * SEQ;
    const __half* Bh = g_vth + ((size_t)b * CH + c0) * SEQ;
    const __half* Bl = g_vtl + ((size_t)b * CH + c0) * SEQ;

    float acc[2][8][4] = {};
    gemm_main(sbase, (t0 + 128) / 32, A, Bh, Bl, SEQ, SEQ, tid,
              wm0, wn0, acc);

    const int qrow = lane >> 2, qcol = (lane & 3) * 2;
    #pragma unroll
    for (int mi = 0; mi < 2; mi++)
        #pragma unroll
        for (int ni = 0; ni < 8; ni++)
            #pragma unroll
            for (int h = 0; h < 2; h++) {
                int t = t0 + wm0 + mi*16 + qrow + h*8;
                int c = c0 + wn0 + ni*8 + qcol;
                *(float2*)&out[((size_t)b * SEQ + t) * CH + c] =
                    make_float2(acc[mi][ni][h*2], acc[mi][ni][h*2+1]);
            }
}

// ---------------------------------------------------------------------------
extern "C" void kernel_launch(void* const* d_in, const int* in_sizes, int n_in,
                              void* d_out, int out_size)
{
    const float* x  = (const float*)d_in[0];
    const float* Wq = (const float*)d_in[1];
    const float* Wk = (const float*)d_in[2];
    const float* Wv = (const float*)d_in[3];
    float* out = (float*)d_out;

    cudaFuncSetAttribute(qkv_kernel,
                         cudaFuncAttributeMaxDynamicSharedMemorySize, SMEM_TOT);
    cudaFuncSetAttribute(scores_kernel,
                         cudaFuncAttributeMaxDynamicSharedMemorySize, SMEM_TOT);
    cudaFuncSetAttribute(pv_kernel,
                         cudaFuncAttributeMaxDynamicSharedMemorySize, SMEM_TOT);

    const size_t n_split = (size_t)MROWS * CH + 3 * (size_t)CH * CH;
    split_kernel<<<(unsigned)(n_split / 1024), 256>>>(x, Wq, Wk, Wv);

    qkv_kernel<<<dim3(8 * 3, MROWS / 128), 256, SMEM_TOT>>>();
    scores_kernel<<<dim3(SEQ / 128, SEQ / 128, BATCH), 256, SMEM_TOT>>>();
    softmax_kernel<<<dim3(SEQ, BATCH), 256>>>();
    pv_kernel<<<dim3(CH / 128, SEQ / 128, BATCH), 256, SMEM_TOT>>>(out);
}

// round 15
// speedup vs baseline: 5.4902x; 1.5990x over previous
#include <cuda_runtime.h>
#include <cuda_fp16.h>
#include <math_constants.h>
#include <cstdint>

#define BATCH 4
#define SEQ   2048
#define CH    1024
#define MROWS (BATCH * SEQ)   // 8192

// ---------------- scratch (device globals; allocation-free) ----------------
static __device__ __half g_xh[(size_t)MROWS * CH];            // x fp16
static __device__ __half g_wh[(size_t)3 * CH * CH];           // W fp16
static __device__ __half g_qh[(size_t)MROWS * CH];            // Q fp16
static __device__ __half g_kh[(size_t)MROWS * CH];            // K fp16
static __device__ __half g_vth[(size_t)BATCH * CH * SEQ];     // V^T fp16
static __device__ float  g_S [(size_t)BATCH * SEQ * SEQ];
static __device__ __half g_ph[(size_t)BATCH * SEQ * SEQ];     // P fp16

// ---------------- baseline-PTX helpers ----------------
__device__ __forceinline__ uint32_t su32(const void* p) {
    uint32_t a;
    asm("{ .reg .u64 t; cvta.to.shared.u64 t, %1; cvt.u32.u64 %0, t; }"
        : "=r"(a) : "l"(p));
    return a;
}
__device__ __forceinline__ void cpasync16(uint32_t dst, const void* src) {
    asm volatile("cp.async.cg.shared.global [%0], [%1], 16;"
                 :: "r"(dst), "l"(src) : "memory");
}
__device__ __forceinline__ void cpcommit() {
    asm volatile("cp.async.commit_group;" ::: "memory");
}
template<int N> __device__ __forceinline__ void cpwait() {
    asm volatile("cp.async.wait_group %0;" :: "n"(N) : "memory");
}
__device__ __forceinline__ void ldsm4(uint32_t* r, uint32_t addr) {
    asm volatile("ldmatrix.sync.aligned.m8n8.x4.shared.b16 {%0,%1,%2,%3}, [%4];"
                 : "=r"(r[0]), "=r"(r[1]), "=r"(r[2]), "=r"(r[3]) : "r"(addr));
}
__device__ __forceinline__ void mma16816(float* d, const uint32_t* a,
                                         const uint32_t* b) {
    asm volatile(
        "mma.sync.aligned.m16n8k16.row.col.f32.f16.f16.f32 "
        "{%0,%1,%2,%3},{%4,%5,%6,%7},{%8,%9},{%0,%1,%2,%3};"
        : "+f"(d[0]), "+f"(d[1]), "+f"(d[2]), "+f"(d[3])
        : "r"(a[0]), "r"(a[1]), "r"(a[2]), "r"(a[3]), "r"(b[0]), "r"(b[1]));
}
__device__ __forceinline__ uint32_t pk(__half a, __half b) {
    uint16_t x = reinterpret_cast<uint16_t&>(a);
    uint16_t y = reinterpret_cast<uint16_t&>(b);
    return (uint32_t)x | ((uint32_t)y << 16);
}

// ---------------- smem tile geometry ----------------
// Tiles: 128 rows x 32 halves (64 B data), padded stride 80 B.
// Stage: A 0, B 10240. Stage size 20480. 2 stages = 40960 B.
#define T_STRIDE 80
#define OFF_B    10240
#define STAGE_SZ 20480
#define SMEM_TOT (2 * STAGE_SZ)

__device__ __forceinline__ void tile_ld(uint32_t sdst, const __half* src,
                                        int ld, int tid) {
    #pragma unroll
    for (int it = 0; it < 2; it++) {
        int u = tid + it * 256;
        int r = u >> 2, q = u & 3;
        cpasync16(sdst + r * T_STRIDE + q * 16, src + (size_t)r * ld + q * 8);
    }
}
__device__ __forceinline__ void chunk_ld(uint32_t sbase, int st,
                                         const __half* A, const __half* B,
                                         int lda, int ldb, int k0, int tid) {
    const uint32_t s = sbase + st * STAGE_SZ;
    tile_ld(s,         A + k0, lda, tid);
    tile_ld(s + OFF_B, B + k0, ldb, tid);
    cpcommit();
}
// one 128x128 x k32 chunk; warp tile 32x64; single fp16 term.
__device__ __forceinline__ void compute_chunk(uint32_t sb, int wm0, int wn0,
                                              int lane, float acc[2][8][4]) {
    const int rowoff = lane & 15;
    const int koff   = (lane >> 4) * 16;
    #pragma unroll
    for (int ks = 0; ks < 2; ks++) {
        const int kb = ks * 32 + koff;
        uint32_t ah[2][4], bb[8][2];
        #pragma unroll
        for (int mi = 0; mi < 2; mi++)
            ldsm4(ah[mi], sb + (uint32_t)(wm0 + mi * 16 + rowoff) * T_STRIDE + kb);
        #pragma unroll
        for (int nf = 0; nf < 4; nf++) {
            uint32_t r4[4];
            ldsm4(r4, sb + OFF_B + (uint32_t)(wn0 + nf * 16 + rowoff) * T_STRIDE + kb);
            bb[nf*2][0] = r4[0]; bb[nf*2+1][0] = r4[1];
            bb[nf*2][1] = r4[2]; bb[nf*2+1][1] = r4[3];
        }
        #pragma unroll
        for (int mi = 0; mi < 2; mi++)
            #pragma unroll
            for (int ni = 0; ni < 8; ni++)
                mma16816(acc[mi][ni], ah[mi], bb[ni]);
    }
}
__device__ __forceinline__ void gemm_main(uint32_t sbase, int NK,
                                          const __half* A, const __half* B,
                                          int lda, int ldb, int tid,
                                          int wm0, int wn0, float acc[2][8][4]) {
    const int lane = tid & 31;
    chunk_ld(sbase, 0, A, B, lda, ldb, 0, tid);
    for (int kc = 0; kc < NK; kc++) {
        if (kc + 1 < NK) {
            chunk_ld(sbase, (kc + 1) & 1, A, B, lda, ldb, (kc + 1) * 32, tid);
            cpwait<1>();
        } else {
            cpwait<0>();
        }
        __syncthreads();
        compute_chunk(sbase + (kc & 1) * STAGE_SZ, wm0, wn0, lane, acc);
        __syncthreads();
    }
}

// ---------------------------------------------------------------------------
// Kernel 0: convert all fp32 inputs to fp16 (single launch).
// ---------------------------------------------------------------------------
__global__ __launch_bounds__(256) void split_kernel(
    const float* __restrict__ x,  const float* __restrict__ Wq,
    const float* __restrict__ Wk, const float* __restrict__ Wv) {
    const size_t NX = (size_t)MROWS * CH;
    const size_t NW = (size_t)CH * CH;
    size_t i = ((size_t)blockIdx.x * 256 + threadIdx.x) * 4;

    const float* src;
    __half* dst;
    size_t off;
    if (i < NX)             { src = x;  dst = g_xh; off = i; }
    else if (i < NX + NW)   { src = Wq; dst = g_wh; off = i - NX;
                              src += off - off; }
    else if (i < NX + 2*NW) { src = Wk; dst = g_wh; off = i - NX; }
    else if (i < NX + 3*NW) { src = Wv; dst = g_wh; off = i - NX; }
    else return;
    size_t loc = (i < NX) ? off
               : (i < NX + NW) ? off
               : (i < NX + 2*NW) ? off - NW : off - 2*NW;

    float4 v = *(const float4*)(src + loc);
    *(uint32_t*)(dst + off)     = pk(__float2half(v.x), __float2half(v.y));
    *(uint32_t*)(dst + off + 2) = pk(__float2half(v.z), __float2half(v.w));
}

// ---------------------------------------------------------------------------
// Kernel 1: QKV = xh * Wh. grid (8*3, 64). Q,K fp16; V transposed fp16.
// ---------------------------------------------------------------------------
__global__ __launch_bounds__(256, 2) void qkv_kernel() {
    extern __shared__ char sm[];
    const int tid = threadIdx.x, wid = tid >> 5, lane = tid & 31;
    const int mat = blockIdx.x >> 3;
    const int n0  = (blockIdx.x & 7) * 128;
    const int m0  = blockIdx.y * 128;
    const int wm0 = (wid & 3) * 32, wn0 = (wid >> 2) * 64;
    const uint32_t sbase = su32(sm);

    const __half* A = g_xh + (size_t)m0 * CH;
    const __half* B = g_wh + (size_t)mat * CH * CH + (size_t)n0 * CH;

    float acc[2][8][4] = {};
    gemm_main(sbase, CH / 32, A, B, CH, CH, tid, wm0, wn0, acc);

    const int qrow = lane >> 2, qcol = (lane & 3) * 2;
    if (mat < 2) {
        __half* Hd = mat ? g_kh : g_qh;
        #pragma unroll
        for (int mi = 0; mi < 2; mi++)
            #pragma unroll
            for (int ni = 0; ni < 8; ni++)
                #pragma unroll
                for (int h = 0; h < 2; h++) {
                    int row = m0 + wm0 + mi*16 + qrow + h*8;
                    int col = n0 + wn0 + ni*8 + qcol;
                    *(uint32_t*)&Hd[(size_t)row * CH + col] =
                        pk(__float2half(acc[mi][ni][h*2]),
                           __float2half(acc[mi][ni][h*2+1]));
                }
    } else {
        #pragma unroll
        for (int mi = 0; mi < 2; mi++)
            #pragma unroll
            for (int ni = 0; ni < 8; ni++)
                #pragma unroll
                for (int h = 0; h < 2; h++) {
                    int row = m0 + wm0 + mi*16 + qrow + h*8;   // token
                    int b = row >> 11, t = row & (SEQ - 1);
                    int col = n0 + wn0 + ni*8 + qcol;          // channel
                    #pragma unroll
                    for (int j = 0; j < 2; j++) {
                        size_t idx = ((size_t)b * CH + col + j) * SEQ + t;
                        g_vth[idx] = __float2half(acc[mi][ni][h*2+j]);
                    }
                }
    }
}

// ---------------------------------------------------------------------------
// Kernel 2: scores = (1/32) * Qh * Kh^T. Skip strictly-upper tiles.
// ---------------------------------------------------------------------------
__global__ __launch_bounds__(256, 2) void scores_kernel() {
    if (blockIdx.x > blockIdx.y) return;
    extern __shared__ char sm[];
    const int tid = threadIdx.x, wid = tid >> 5, lane = tid & 31;
    const int b  = blockIdx.z;
    const int s0 = blockIdx.x * 128;
    const int t0 = blockIdx.y * 128;
    const int wm0 = (wid & 3) * 32, wn0 = (wid >> 2) * 64;
    const uint32_t sbase = su32(sm);

    const size_t ar = (size_t)(b * SEQ + t0) * CH;
    const size_t br = (size_t)(b * SEQ + s0) * CH;

    float acc[2][8][4] = {};
    gemm_main(sbase, CH / 32, g_qh + ar, g_kh + br, CH, CH, tid, wm0, wn0, acc);

    const int qrow = lane >> 2, qcol = (lane & 3) * 2;
    const float scl = 0.03125f;
    #pragma unroll
    for (int mi = 0; mi < 2; mi++)
        #pragma unroll
        for (int ni = 0; ni < 8; ni++)
            #pragma unroll
            for (int h = 0; h < 2; h++) {
                int t = t0 + wm0 + mi*16 + qrow + h*8;
                int s = s0 + wn0 + ni*8 + qcol;
                *(float2*)&g_S[((size_t)b * SEQ + t) * SEQ + s] =
                    make_float2(acc[mi][ni][h*2] * scl, acc[mi][ni][h*2+1] * scl);
            }
}

// ---------------------------------------------------------------------------
// Kernel 3: row softmax; writes P fp16, zeros to 128-tile boundary.
// ---------------------------------------------------------------------------
__global__ __launch_bounds__(256) void softmax_kernel() {
    const int t = blockIdx.x;
    const int b = blockIdx.y;
    const size_t rowb = ((size_t)b * SEQ + t) * SEQ;
    const float* Srow = g_S + rowb;
    const int tid = threadIdx.x;
    const int len = ((t >> 7) + 1) << 7;

    float v[8];
    float m = -CUDART_INF_F;
    #pragma unroll
    for (int i = 0; i < 8; i++) {
        int s = tid + i * 256;
        v[i] = (s <= t) ? Srow[s] : -CUDART_INF_F;
        m = fmaxf(m, v[i]);
    }
    #pragma unroll
    for (int o = 16; o; o >>= 1) m = fmaxf(m, __shfl_xor_sync(~0u, m, o));
    __shared__ float smax[8], ssum[8];
    if ((tid & 31) == 0) smax[tid >> 5] = m;
    __syncthreads();
    m = smax[0];
    #pragma unroll
    for (int i = 1; i < 8; i++) m = fmaxf(m, smax[i]);

    float s = 0.f;
    #pragma unroll
    for (int i = 0; i < 8; i++) { v[i] = expf(v[i] - m); s += v[i]; }
    #pragma unroll
    for (int o = 16; o; o >>= 1) s += __shfl_xor_sync(~0u, s, o);
    if ((tid & 31) == 0) ssum[tid >> 5] = s;
    __syncthreads();
    s = 0.f;
    #pragma unroll
    for (int i = 0; i < 8; i++) s += ssum[i];
    const float inv = 1.0f / s;

    #pragma unroll
    for (int i = 0; i < 8; i++) {
        int sc = tid + i * 256;
        if (sc < len) g_ph[rowb + sc] = __float2half(v[i] * inv);
    }
}

// ---------------------------------------------------------------------------
// Kernel 4: O = Ph * Vh^T. K clipped at t0+128.
// ---------------------------------------------------------------------------
__global__ __launch_bounds__(256, 2) void pv_kernel(float* __restrict__ out) {
    extern __shared__ char sm[];
    const int tid = threadIdx.x, wid = tid >> 5, lane = tid & 31;
    const int b  = blockIdx.z;
    const int c0 = blockIdx.x * 128;
    const int t0 = blockIdx.y * 128;
    const int wm0 = (wid & 3) * 32, wn0 = (wid >> 2) * 64;
    const uint32_t sbase = su32(sm);

    const __half* A = g_ph  + ((size_t)b * SEQ + t0) * SEQ;
    const __half* B = g_vth + ((size_t)b * CH + c0) * SEQ;

    float acc[2][8][4] = {};
    gemm_main(sbase, (t0 + 128) / 32, A, B, SEQ, SEQ, tid, wm0, wn0, acc);

    const int qrow = lane >> 2, qcol = (lane & 3) * 2;
    #pragma unroll
    for (int mi = 0; mi < 2; mi++)
        #pragma unroll
        for (int ni = 0; ni < 8; ni++)
            #pragma unroll
            for (int h = 0; h < 2; h++) {
                int t = t0 + wm0 + mi*16 + qrow + h*8;
                int c = c0 + wn0 + ni*8 + qcol;
                *(float2*)&out[((size_t)b * SEQ + t) * CH + c] =
                    make_float2(acc[mi][ni][h*2], acc[mi][ni][h*2+1]);
            }
}

// ---------------------------------------------------------------------------
extern "C" void kernel_launch(void* const* d_in, const int* in_sizes, int n_in,
                              void* d_out, int out_size)
{
    const float* x  = (const float*)d_in[0];
    const float* Wq = (const float*)d_in[1];
    const float* Wk = (const float*)d_in[2];
    const float* Wv = (const float*)d_in[3];
    float* out = (float*)d_out;

    cudaFuncSetAttribute(qkv_kernel,
                         cudaFuncAttributeMaxDynamicSharedMemorySize, SMEM_TOT);
    cudaFuncSetAttribute(scores_kernel,
                         cudaFuncAttributeMaxDynamicSharedMemorySize, SMEM_TOT);
    cudaFuncSetAttribute(pv_kernel,
                         cudaFuncAttributeMaxDynamicSharedMemorySize, SMEM_TOT);

    const size_t n_split = (size_t)MROWS * CH + 3 * (size_t)CH * CH;
    split_kernel<<<(unsigned)(n_split / 1024), 256>>>(x, Wq, Wk, Wv);

    qkv_kernel<<<dim3(8 * 3, MROWS / 128), 256, SMEM_TOT>>>();
    scores_kernel<<<dim3(SEQ / 128, SEQ / 128, BATCH), 256, SMEM_TOT>>>();
    softmax_kernel<<<dim3(SEQ, BATCH), 256>>>();
    pv_kernel<<<dim3(CH / 128, SEQ / 128, BATCH), 256, SMEM_TOT>>>(out);
}